// round 1
// baseline (speedup 1.0000x reference)
#include <cuda_runtime.h>

#define F 256
#define NTOK 1024
#define NB 16
#define ROWS (NB*NTOK)   // 16384

// Scratch (device globals — no allocation allowed)
__device__ float g_alpha[ROWS*F];
__device__ float g_beta[ROWS*F];
__device__ float g_up[ROWS*F];      // u' = unary @ W_r^T computed directly from x
__device__ float g_Mp[NB*F*F];      // M'[b][k][g] = sum_n beta[b,n,k] * up[b,n,g]
__device__ float g_d[ROWS];         // d[i] = alpha_i . beta_i
__device__ float g_Wur[F*F];        // W_r @ W_unary
__device__ float g_bp[F];           // W_r @ b_unary

// ---------------------------------------------------------------------------
// K0: combined weight W_ur[g,f] = sum_h W_r[g,h] * W_u[h,f];  b'[g] = sum_h W_r[g,h]*b[h]
// ---------------------------------------------------------------------------
__global__ void k0_combine(const float* __restrict__ Wr,
                           const float* __restrict__ Wu,
                           const float* __restrict__ bu) {
    __shared__ float sWr[F];
    int g = blockIdx.x;
    int f = threadIdx.x;
    sWr[f] = Wr[g*F + f];
    __syncthreads();
    float acc = 0.f;
    #pragma unroll 8
    for (int h = 0; h < F; ++h) acc = fmaf(sWr[h], Wu[h*F + f], acc);
    g_Wur[g*F + f] = acc;
    if (f == 0) {
        float bb = 0.f;
        for (int h = 0; h < F; ++h) bb = fmaf(sWr[h], bu[h], bb);
        g_bp[g] = bb;
    }
}

// ---------------------------------------------------------------------------
// K1: projections. out[n,g] = sum_f x[n,f] * W[g,f] (+bias for z==2)
// z=0: alpha (W_alpha), z=1: beta (W_beta), z=2: up (g_Wur + g_bp)
// 128x128 tile, 8x8 microtile, BK=16, k-major smem tiles (conflict-free).
// ---------------------------------------------------------------------------
__global__ __launch_bounds__(256) void k1_proj(
    const float* __restrict__ x,
    const float* __restrict__ Wa,
    const float* __restrict__ Wb)
{
    const int z = blockIdx.z;
    const float* __restrict__ W = (z==0) ? Wa : (z==1) ? Wb : g_Wur;
    float* __restrict__ out = (z==0) ? g_alpha : (z==1) ? g_beta : g_up;

    __shared__ float As[16][129];
    __shared__ float Bs[16][129];

    const int row0 = blockIdx.x * 128;
    const int col0 = blockIdx.y * 128;
    const int tid = threadIdx.x;
    const int tx = tid & 15, ty = tid >> 4;

    float acc[8][8];
    #pragma unroll
    for (int i = 0; i < 8; ++i)
        #pragma unroll
        for (int j = 0; j < 8; ++j) acc[i][j] = 0.f;

    for (int kt = 0; kt < F; kt += 16) {
        #pragma unroll
        for (int l = 0; l < 8; ++l) {
            int idx = tid + l*256;
            int r = idx >> 4, k = idx & 15;
            As[k][r] = x[(row0 + r)*F + kt + k];
            Bs[k][r] = W[(col0 + r)*F + kt + k];
        }
        __syncthreads();
        #pragma unroll
        for (int k = 0; k < 16; ++k) {
            float a[8], b[8];
            #pragma unroll
            for (int i = 0; i < 8; ++i) a[i] = As[k][ty + 16*i];
            #pragma unroll
            for (int j = 0; j < 8; ++j) b[j] = Bs[k][tx + 16*j];
            #pragma unroll
            for (int i = 0; i < 8; ++i)
                #pragma unroll
                for (int j = 0; j < 8; ++j)
                    acc[i][j] = fmaf(a[i], b[j], acc[i][j]);
        }
        __syncthreads();
    }

    #pragma unroll
    for (int i = 0; i < 8; ++i) {
        int r = row0 + ty + 16*i;
        #pragma unroll
        for (int j = 0; j < 8; ++j) {
            int c = col0 + tx + 16*j;
            float v = acc[i][j];
            if (z == 2) v += g_bp[c];
            out[r*F + c] = v;
        }
    }
}

// ---------------------------------------------------------------------------
// K2: M'[b][k][g] = sum_{n<1024} beta[b,n,k] * up[b,n,g]
// 64x64 tile, 4x4 microtile, 16-n chunks. grid (4,4,16) = 256 blocks.
// ---------------------------------------------------------------------------
__global__ __launch_bounds__(256) void k2_mprime() {
    const int b  = blockIdx.z;
    const int k0 = blockIdx.x * 64;
    const int g0 = blockIdx.y * 64;
    const float* __restrict__ beta = g_beta + b*NTOK*F;
    const float* __restrict__ up   = g_up   + b*NTOK*F;
    __shared__ float Bs[16][64];
    __shared__ float Us[16][64];
    const int tid = threadIdx.x;
    const int tx = tid & 15, ty = tid >> 4;
    float acc[4][4];
    #pragma unroll
    for (int i = 0; i < 4; ++i)
        #pragma unroll
        for (int j = 0; j < 4; ++j) acc[i][j] = 0.f;

    for (int nt = 0; nt < NTOK; nt += 16) {
        #pragma unroll
        for (int l = 0; l < 4; ++l) {
            int idx = tid + l*256;
            int n = idx >> 6, c = idx & 63;
            Bs[n][c] = beta[(nt+n)*F + k0 + c];
            Us[n][c] = up[(nt+n)*F + g0 + c];
        }
        __syncthreads();
        #pragma unroll
        for (int n = 0; n < 16; ++n) {
            float a[4], bb[4];
            #pragma unroll
            for (int i = 0; i < 4; ++i) a[i] = Bs[n][ty + 16*i];
            #pragma unroll
            for (int j = 0; j < 4; ++j) bb[j] = Us[n][tx + 16*j];
            #pragma unroll
            for (int i = 0; i < 4; ++i)
                #pragma unroll
                for (int j = 0; j < 4; ++j)
                    acc[i][j] = fmaf(a[i], bb[j], acc[i][j]);
        }
        __syncthreads();
    }
    #pragma unroll
    for (int i = 0; i < 4; ++i)
        #pragma unroll
        for (int j = 0; j < 4; ++j)
            g_Mp[b*F*F + (k0 + ty + 16*i)*F + g0 + tx + 16*j] = acc[i][j];
}

// ---------------------------------------------------------------------------
// K2b: d[i] = alpha_i . beta_i   (one warp per row)
// ---------------------------------------------------------------------------
__global__ void k2b_diag() {
    int row  = (blockIdx.x * blockDim.x + threadIdx.x) >> 5;
    int lane = threadIdx.x & 31;
    const float* a  = g_alpha + row*F;
    const float* bt = g_beta  + row*F;
    float s = 0.f;
    #pragma unroll
    for (int k = lane; k < F; k += 32) s = fmaf(a[k], bt[k], s);
    #pragma unroll
    for (int o = 16; o > 0; o >>= 1) s += __shfl_xor_sync(0xffffffffu, s, o);
    if (lane == 0) g_d[row] = s;
}

// ---------------------------------------------------------------------------
// K3: out[i,g] = (sum_k alpha[i,k]*M'[b][k][g] - d[i]*up[i,g]) / 1024 + x[i,g]
// 128x128 tile, 8x8 microtile, BK=16.
// ---------------------------------------------------------------------------
__global__ __launch_bounds__(256) void k3_out(
    const float* __restrict__ x, float* __restrict__ out)
{
    const int row0 = blockIdx.x * 128;
    const int col0 = blockIdx.y * 128;
    const int b = row0 >> 10;                 // 1024 rows per batch, tiles aligned
    const float* __restrict__ Mp = g_Mp + b*F*F;

    __shared__ float As[16][129];
    __shared__ float Ms[16][129];

    const int tid = threadIdx.x;
    const int tx = tid & 15, ty = tid >> 4;

    float acc[8][8];
    #pragma unroll
    for (int i = 0; i < 8; ++i)
        #pragma unroll
        for (int j = 0; j < 8; ++j) acc[i][j] = 0.f;

    for (int kt = 0; kt < F; kt += 16) {
        #pragma unroll
        for (int l = 0; l < 8; ++l) {
            int idx = tid + l*256;
            {
                int r = idx >> 4, k = idx & 15;
                As[k][r] = g_alpha[(row0 + r)*F + kt + k];
            }
            {
                int k = idx >> 7, c = idx & 127;
                Ms[k][c] = Mp[(kt + k)*F + col0 + c];
            }
        }
        __syncthreads();
        #pragma unroll
        for (int k = 0; k < 16; ++k) {
            float a[8], mb[8];
            #pragma unroll
            for (int i = 0; i < 8; ++i) a[i] = As[k][ty + 16*i];
            #pragma unroll
            for (int j = 0; j < 8; ++j) mb[j] = Ms[k][tx + 16*j];
            #pragma unroll
            for (int i = 0; i < 8; ++i)
                #pragma unroll
                for (int j = 0; j < 8; ++j)
                    acc[i][j] = fmaf(a[i], mb[j], acc[i][j]);
        }
        __syncthreads();
    }

    const float inv = 1.0f / (float)NTOK;
    #pragma unroll
    for (int i = 0; i < 8; ++i) {
        int r = row0 + ty + 16*i;
        float di = g_d[r];
        #pragma unroll
        for (int j = 0; j < 8; ++j) {
            int c = col0 + tx + 16*j;
            float v = (acc[i][j] - di * g_up[r*F + c]) * inv + x[r*F + c];
            out[r*F + c] = v;
        }
    }
}

// ---------------------------------------------------------------------------
extern "C" void kernel_launch(void* const* d_in, const int* in_sizes, int n_in,
                              void* d_out, int out_size) {
    const float* x  = (const float*)d_in[0];
    const float* Wa = (const float*)d_in[1];
    const float* Wb = (const float*)d_in[2];
    const float* Wu = (const float*)d_in[3];
    const float* bu = (const float*)d_in[4];
    const float* Wr = (const float*)d_in[5];
    float* out = (float*)d_out;

    k0_combine<<<F, F>>>(Wr, Wu, bu);
    k1_proj<<<dim3(ROWS/128, F/128, 3), 256>>>(x, Wa, Wb);
    k2_mprime<<<dim3(F/64, F/64, NB), 256>>>();
    k2b_diag<<<ROWS/8, 256>>>();
    k3_out<<<dim3(ROWS/128, F/128), 256>>>(x, out);
}

// round 2
// speedup vs baseline: 3.6023x; 3.6023x over previous
#include <cuda_runtime.h>
#include <cuda_bf16.h>
#include <cstdint>

#define F 256
#define NTOK 1024
#define NB 16
#define ROWS (NB*NTOK)   // 16384

// ---------------- scratch (device globals; no allocation allowed) ----------
__device__ __nv_bfloat16 g_xb[ROWS*F];       // x in bf16
__device__ __nv_bfloat16 g_alpha[ROWS*F];
__device__ __nv_bfloat16 g_beta[ROWS*F];
__device__ __nv_bfloat16 g_up[ROWS*F];       // u' = x @ (W_r W_u)^T + W_r b
__device__ __nv_bfloat16 g_Mp[NB*F*F];       // M'[b][k][g] = sum_n beta[b,n,k]*up[b,n,g]
__device__ __nv_bfloat16 g_Wbf[3*F*F];       // Wa | Wb | Wur  (bf16)
__device__ float g_Wur[F*F];                 // fp32 combined weight
__device__ float g_bp[F];
__device__ float g_d[ROWS];                  // d_i = alpha_i . beta_i

// ---------------- mma / ldmatrix helpers -----------------------------------
__device__ __forceinline__ uint32_t cvta_s(const void* p) {
    return (uint32_t)__cvta_generic_to_shared(p);
}
__device__ __forceinline__ void ldmx4(uint32_t r[4], uint32_t addr) {
    asm volatile("ldmatrix.sync.aligned.m8n8.x4.shared.b16 {%0,%1,%2,%3}, [%4];\n"
        : "=r"(r[0]), "=r"(r[1]), "=r"(r[2]), "=r"(r[3]) : "r"(addr));
}
__device__ __forceinline__ void ldmx4t(uint32_t r[4], uint32_t addr) {
    asm volatile("ldmatrix.sync.aligned.m8n8.x4.trans.shared.b16 {%0,%1,%2,%3}, [%4];\n"
        : "=r"(r[0]), "=r"(r[1]), "=r"(r[2]), "=r"(r[3]) : "r"(addr));
}
__device__ __forceinline__ void mma_bf16(float c[4], const uint32_t a[4], const uint32_t b[2]) {
    asm volatile(
        "mma.sync.aligned.m16n8k16.row.col.f32.bf16.bf16.f32 "
        "{%0,%1,%2,%3}, {%4,%5,%6,%7}, {%8,%9}, {%0,%1,%2,%3};\n"
        : "+f"(c[0]), "+f"(c[1]), "+f"(c[2]), "+f"(c[3])
        : "r"(a[0]), "r"(a[1]), "r"(a[2]), "r"(a[3]), "r"(b[0]), "r"(b[1]));
}

// ---------------- K0: combined weight (fp32) --------------------------------
__global__ void k0_combine(const float* __restrict__ Wr,
                           const float* __restrict__ Wu,
                           const float* __restrict__ bu) {
    __shared__ float sWr[F];
    int g = blockIdx.x;
    int f = threadIdx.x;
    sWr[f] = Wr[g*F + f];
    __syncthreads();
    float acc = 0.f;
    #pragma unroll 8
    for (int h = 0; h < F; ++h) acc = fmaf(sWr[h], Wu[h*F + f], acc);
    g_Wur[g*F + f] = acc;
    if (f == 0) {
        float bb = 0.f;
        for (int h = 0; h < F; ++h) bb = fmaf(sWr[h], bu[h], bb);
        g_bp[g] = bb;
    }
}

// ---------------- conversions ------------------------------------------------
__global__ void kconv_x(const float* __restrict__ x) {
    int i = blockIdx.x * blockDim.x + threadIdx.x;           // float4 index
    float4 v = ((const float4*)x)[i];
    ((__nv_bfloat162*)g_xb)[2*i]   = __floats2bfloat162_rn(v.x, v.y);
    ((__nv_bfloat162*)g_xb)[2*i+1] = __floats2bfloat162_rn(v.z, v.w);
}
__global__ void kconv_w(const float* __restrict__ Wa, const float* __restrict__ Wb) {
    int i = blockIdx.x * blockDim.x + threadIdx.x;           // float4 index, 3*16384
    const float* src = (i < 16384) ? Wa : (i < 32768) ? Wb : (const float*)g_Wur;
    int j = i & 16383;
    float4 v = ((const float4*)src)[j];
    ((__nv_bfloat162*)g_Wbf)[2*i]   = __floats2bfloat162_rn(v.x, v.y);
    ((__nv_bfloat162*)g_Wbf)[2*i+1] = __floats2bfloat162_rn(v.z, v.w);
}

// ---------------- G1: projections via HMMA ----------------------------------
// out[n,g] = sum_f xb[n,f] * W[g,f]  (+bias for z==2), output bf16.
// 128x128 tile, BK=32, 8 warps (2m x 4n), warp tile 64x32.
__global__ __launch_bounds__(256) void g1_proj() {
    const int z = blockIdx.z;
    const __nv_bfloat16* __restrict__ W = g_Wbf + z*F*F;
    __nv_bfloat16* __restrict__ out = (z == 0) ? g_alpha : (z == 1) ? g_beta : g_up;

    const int row0 = blockIdx.x * 128;
    const int col0 = blockIdx.y * 128;
    __shared__ __nv_bfloat16 As[128][40];
    __shared__ __nv_bfloat16 Bs[128][40];

    const int tid = threadIdx.x, lane = tid & 31, wid = tid >> 5;
    const int wm = wid & 1, wn = wid >> 1;

    float acc[4][4][4];
    #pragma unroll
    for (int i = 0; i < 4; ++i)
        #pragma unroll
        for (int j = 0; j < 4; ++j)
            #pragma unroll
            for (int e = 0; e < 4; ++e) acc[i][j][e] = 0.f;

    for (int kt = 0; kt < F; kt += 32) {
        #pragma unroll
        for (int l = 0; l < 2; ++l) {
            int idx = tid + l*256;
            int r = idx >> 2, c8 = (idx & 3) * 8;
            *(uint4*)&As[r][c8] = *(const uint4*)&g_xb[(row0 + r)*F + kt + c8];
            *(uint4*)&Bs[r][c8] = *(const uint4*)&W[(col0 + r)*F + kt + c8];
        }
        __syncthreads();
        #pragma unroll
        for (int ks = 0; ks < 2; ++ks) {
            const int k0 = ks * 16;
            uint32_t a[4][4];
            #pragma unroll
            for (int mt = 0; mt < 4; ++mt)
                ldmx4(a[mt], cvta_s(&As[wm*64 + mt*16 + (lane & 15)][k0 + (lane >> 4)*8]));
            uint32_t b[4][2];
            #pragma unroll
            for (int bt = 0; bt < 2; ++bt) {
                uint32_t t[4];
                int n  = wn*32 + bt*16 + (lane & 7) + ((lane >> 4) & 1)*8;
                int kk = k0 + ((lane >> 3) & 1)*8;
                ldmx4(t, cvta_s(&Bs[n][kk]));
                b[bt*2][0] = t[0]; b[bt*2][1] = t[1];
                b[bt*2+1][0] = t[2]; b[bt*2+1][1] = t[3];
            }
            #pragma unroll
            for (int mt = 0; mt < 4; ++mt)
                #pragma unroll
                for (int nt = 0; nt < 4; ++nt)
                    mma_bf16(acc[mt][nt], a[mt], b[nt]);
        }
        __syncthreads();
    }

    const int rc = lane >> 2, cc = (lane & 3)*2;
    #pragma unroll
    for (int mt = 0; mt < 4; ++mt) {
        int rb = row0 + wm*64 + mt*16 + rc;
        #pragma unroll
        for (int nt = 0; nt < 4; ++nt) {
            int col = col0 + wn*32 + nt*8 + cc;
            #pragma unroll
            for (int h = 0; h < 2; ++h) {
                int row = rb + h*8;
                float v0 = acc[mt][nt][2*h], v1 = acc[mt][nt][2*h+1];
                if (z == 2) { v0 += g_bp[col]; v1 += g_bp[col+1]; }
                *(__nv_bfloat162*)&out[row*F + col] = __floats2bfloat162_rn(v0, v1);
            }
        }
    }
}

// ---------------- K diag: d_i = alpha_i . beta_i -----------------------------
__global__ void kdiag() {
    int gw = (blockIdx.x * blockDim.x + threadIdx.x) >> 5;
    int lane = threadIdx.x & 31;
    const __nv_bfloat162* a = (const __nv_bfloat162*)(g_alpha + gw*F);
    const __nv_bfloat162* b = (const __nv_bfloat162*)(g_beta  + gw*F);
    float s = 0.f;
    #pragma unroll
    for (int t = lane; t < 128; t += 32) {
        float2 av = __bfloat1622float2(a[t]);
        float2 bv = __bfloat1622float2(b[t]);
        s = fmaf(av.x, bv.x, s);
        s = fmaf(av.y, bv.y, s);
    }
    #pragma unroll
    for (int o = 16; o > 0; o >>= 1) s += __shfl_xor_sync(0xffffffffu, s, o);
    if (lane == 0) g_d[gw] = s;
}

// ---------------- G2: M'[b][k][g] = sum_r beta[b,r,k] * up[b,r,g] ------------
// Tile 128(m=k-index) x 128(n=g), reduce over r (1024). Both operands trans.
__global__ __launch_bounds__(256) void g2_mprime() {
    const int b  = blockIdx.z;
    const int m0 = blockIdx.x * 128;
    const int n0 = blockIdx.y * 128;
    const __nv_bfloat16* __restrict__ beta = g_beta + b*NTOK*F;
    const __nv_bfloat16* __restrict__ up   = g_up   + b*NTOK*F;

    __shared__ __nv_bfloat16 Bs[32][136];
    __shared__ __nv_bfloat16 Us[32][136];

    const int tid = threadIdx.x, lane = tid & 31, wid = tid >> 5;
    const int wm = wid & 1, wn = wid >> 1;

    float acc[4][4][4];
    #pragma unroll
    for (int i = 0; i < 4; ++i)
        #pragma unroll
        for (int j = 0; j < 4; ++j)
            #pragma unroll
            for (int e = 0; e < 4; ++e) acc[i][j][e] = 0.f;

    for (int rt = 0; rt < NTOK; rt += 32) {
        #pragma unroll
        for (int l = 0; l < 2; ++l) {
            int idx = tid + l*256;
            int r = idx >> 4, c8 = (idx & 15) * 8;
            *(uint4*)&Bs[r][c8] = *(const uint4*)&beta[(rt + r)*F + m0 + c8];
            *(uint4*)&Us[r][c8] = *(const uint4*)&up[(rt + r)*F + n0 + c8];
        }
        __syncthreads();
        #pragma unroll
        for (int ks = 0; ks < 2; ++ks) {
            const int r0 = ks * 16;
            uint32_t a[4][4];
            #pragma unroll
            for (int mt = 0; mt < 4; ++mt) {
                int rr = r0 + (lane & 7) + ((lane >> 4) & 1)*8;
                int cm = wm*64 + mt*16 + ((lane >> 3) & 1)*8;
                ldmx4t(a[mt], cvta_s(&Bs[rr][cm]));
            }
            uint32_t bfr[4][2];
            #pragma unroll
            for (int bt = 0; bt < 2; ++bt) {
                uint32_t t[4];
                int rr = r0 + (lane & 7) + ((lane >> 3) & 1)*8;
                int cn = wn*32 + bt*16 + ((lane >> 4) & 1)*8;
                ldmx4t(t, cvta_s(&Us[rr][cn]));
                bfr[bt*2][0] = t[0]; bfr[bt*2][1] = t[1];
                bfr[bt*2+1][0] = t[2]; bfr[bt*2+1][1] = t[3];
            }
            #pragma unroll
            for (int mt = 0; mt < 4; ++mt)
                #pragma unroll
                for (int nt = 0; nt < 4; ++nt)
                    mma_bf16(acc[mt][nt], a[mt], bfr[nt]);
        }
        __syncthreads();
    }

    const int rc = lane >> 2, cc = (lane & 3)*2;
    __nv_bfloat16* __restrict__ Mp = g_Mp + b*F*F;
    #pragma unroll
    for (int mt = 0; mt < 4; ++mt) {
        int rb = m0 + wm*64 + mt*16 + rc;
        #pragma unroll
        for (int nt = 0; nt < 4; ++nt) {
            int col = n0 + wn*32 + nt*8 + cc;
            #pragma unroll
            for (int h = 0; h < 2; ++h) {
                int row = rb + h*8;
                *(__nv_bfloat162*)&Mp[row*F + col] =
                    __floats2bfloat162_rn(acc[mt][nt][2*h], acc[mt][nt][2*h+1]);
            }
        }
    }
}

// ---------------- G3: out = (alpha @ M' - d*up)/N + x ------------------------
__global__ __launch_bounds__(256) void g3_out(const float* __restrict__ x,
                                              float* __restrict__ out) {
    const int row0 = blockIdx.x * 128;
    const int col0 = blockIdx.y * 128;
    const int b = row0 >> 10;
    const __nv_bfloat16* __restrict__ Mp = g_Mp + b*F*F;

    __shared__ __nv_bfloat16 As[128][40];
    __shared__ __nv_bfloat16 Ms[32][136];

    const int tid = threadIdx.x, lane = tid & 31, wid = tid >> 5;
    const int wm = wid & 1, wn = wid >> 1;

    float acc[4][4][4];
    #pragma unroll
    for (int i = 0; i < 4; ++i)
        #pragma unroll
        for (int j = 0; j < 4; ++j)
            #pragma unroll
            for (int e = 0; e < 4; ++e) acc[i][j][e] = 0.f;

    for (int kt = 0; kt < F; kt += 32) {
        #pragma unroll
        for (int l = 0; l < 2; ++l) {
            int idx = tid + l*256;
            { int r = idx >> 2, c8 = (idx & 3) * 8;
              *(uint4*)&As[r][c8] = *(const uint4*)&g_alpha[(row0 + r)*F + kt + c8]; }
            { int r = idx >> 4, c8 = (idx & 15) * 8;
              *(uint4*)&Ms[r][c8] = *(const uint4*)&Mp[(kt + r)*F + col0 + c8]; }
        }
        __syncthreads();
        #pragma unroll
        for (int ks = 0; ks < 2; ++ks) {
            const int k0 = ks * 16;
            uint32_t a[4][4];
            #pragma unroll
            for (int mt = 0; mt < 4; ++mt)
                ldmx4(a[mt], cvta_s(&As[wm*64 + mt*16 + (lane & 15)][k0 + (lane >> 4)*8]));
            uint32_t bfr[4][2];
            #pragma unroll
            for (int bt = 0; bt < 2; ++bt) {
                uint32_t t[4];
                int rr = k0 + (lane & 7) + ((lane >> 3) & 1)*8;
                int cn = wn*32 + bt*16 + ((lane >> 4) & 1)*8;
                ldmx4t(t, cvta_s(&Ms[rr][cn]));
                bfr[bt*2][0] = t[0]; bfr[bt*2][1] = t[1];
                bfr[bt*2+1][0] = t[2]; bfr[bt*2+1][1] = t[3];
            }
            #pragma unroll
            for (int mt = 0; mt < 4; ++mt)
                #pragma unroll
                for (int nt = 0; nt < 4; ++nt)
                    mma_bf16(acc[mt][nt], a[mt], bfr[nt]);
        }
        __syncthreads();
    }

    const float inv = 1.0f / (float)NTOK;
    const int rc = lane >> 2, cc = (lane & 3)*2;
    #pragma unroll
    for (int mt = 0; mt < 4; ++mt) {
        int rb = row0 + wm*64 + mt*16 + rc;
        #pragma unroll
        for (int h = 0; h < 2; ++h) {
            int row = rb + h*8;
            float di = g_d[row];
            #pragma unroll
            for (int nt = 0; nt < 4; ++nt) {
                int col = col0 + wn*32 + nt*8 + cc;
                float2 uv = __bfloat1622float2(*(const __nv_bfloat162*)&g_up[row*F + col]);
                float2 xv = *(const float2*)&x[row*F + col];
                float2 o;
                o.x = (acc[mt][nt][2*h]   - di*uv.x) * inv + xv.x;
                o.y = (acc[mt][nt][2*h+1] - di*uv.y) * inv + xv.y;
                *(float2*)&out[row*F + col] = o;
            }
        }
    }
}

// ---------------------------------------------------------------------------
extern "C" void kernel_launch(void* const* d_in, const int* in_sizes, int n_in,
                              void* d_out, int out_size) {
    const float* x  = (const float*)d_in[0];
    const float* Wa = (const float*)d_in[1];
    const float* Wb = (const float*)d_in[2];
    const float* Wu = (const float*)d_in[3];
    const float* bu = (const float*)d_in[4];
    const float* Wr = (const float*)d_in[5];
    float* out = (float*)d_out;

    k0_combine<<<F, F>>>(Wr, Wu, bu);
    kconv_x<<<ROWS*F/4/256, 256>>>(x);
    kconv_w<<<3*F*F/4/256, 256>>>(Wa, Wb);
    g1_proj<<<dim3(ROWS/128, F/128, 3), 256>>>();
    kdiag<<<ROWS*32/256, 256>>>();
    g2_mprime<<<dim3(F/128, F/128, NB), 256>>>();
    g3_out<<<dim3(ROWS/128, F/128), 256>>>(x, out);
}

// round 3
// speedup vs baseline: 4.2801x; 1.1882x over previous
#include <cuda_runtime.h>
#include <cuda_bf16.h>
#include <cstdint>

#define F 256
#define NTOK 1024
#define NB 16
#define ROWS (NB*NTOK)   // 16384

// ---------------- scratch (device globals; no allocation allowed) ----------
__device__ __nv_bfloat16 g_xb[ROWS*F];
__device__ __nv_bfloat16 g_alpha[ROWS*F];
__device__ __nv_bfloat16 g_beta[ROWS*F];
__device__ __nv_bfloat16 g_up[ROWS*F];
__device__ __nv_bfloat16 g_Mp[NB*F*F];
__device__ __nv_bfloat16 g_Wbf[3*F*F];
__device__ float g_Wur[F*F];
__device__ float g_bp[F];
__device__ float g_d[ROWS];

// ---------------- helpers ----------------------------------------------------
__device__ __forceinline__ uint32_t cvta_s(const void* p) {
    return (uint32_t)__cvta_generic_to_shared(p);
}
__device__ __forceinline__ void cp16(void* s, const void* g) {
    asm volatile("cp.async.cg.shared.global [%0], [%1], 16;\n"
        :: "r"(cvta_s(s)), "l"(g));
}
__device__ __forceinline__ void cp_commit() { asm volatile("cp.async.commit_group;\n"); }
__device__ __forceinline__ void cp_wait1()  { asm volatile("cp.async.wait_group 1;\n"); }
__device__ __forceinline__ void cp_wait0()  { asm volatile("cp.async.wait_group 0;\n"); }

__device__ __forceinline__ void ldmx4(uint32_t r[4], uint32_t addr) {
    asm volatile("ldmatrix.sync.aligned.m8n8.x4.shared.b16 {%0,%1,%2,%3}, [%4];\n"
        : "=r"(r[0]), "=r"(r[1]), "=r"(r[2]), "=r"(r[3]) : "r"(addr));
}
__device__ __forceinline__ void ldmx4t(uint32_t r[4], uint32_t addr) {
    asm volatile("ldmatrix.sync.aligned.m8n8.x4.trans.shared.b16 {%0,%1,%2,%3}, [%4];\n"
        : "=r"(r[0]), "=r"(r[1]), "=r"(r[2]), "=r"(r[3]) : "r"(addr));
}
__device__ __forceinline__ void mma_bf16(float c[4], const uint32_t a[4], const uint32_t b[2]) {
    asm volatile(
        "mma.sync.aligned.m16n8k16.row.col.f32.bf16.bf16.f32 "
        "{%0,%1,%2,%3}, {%4,%5,%6,%7}, {%8,%9}, {%0,%1,%2,%3};\n"
        : "+f"(c[0]), "+f"(c[1]), "+f"(c[2]), "+f"(c[3])
        : "r"(a[0]), "r"(a[1]), "r"(a[2]), "r"(a[3]), "r"(b[0]), "r"(b[1]));
}

// ---------------- K0: combined weight ---------------------------------------
__global__ void k0_combine(const float* __restrict__ Wr,
                           const float* __restrict__ Wu,
                           const float* __restrict__ bu) {
    __shared__ float sWr[F];
    int g = blockIdx.x;
    int f = threadIdx.x;
    sWr[f] = Wr[g*F + f];
    __syncthreads();
    float acc = 0.f;
    #pragma unroll 8
    for (int h = 0; h < F; ++h) acc = fmaf(sWr[h], Wu[h*F + f], acc);
    g_Wur[g*F + f] = acc;
    if (f == 0) {
        float bb = 0.f;
        for (int h = 0; h < F; ++h) bb = fmaf(sWr[h], bu[h], bb);
        g_bp[g] = bb;
    }
}

// ---------------- conversions ------------------------------------------------
__global__ void kconv_x(const float* __restrict__ x) {
    int i = blockIdx.x * blockDim.x + threadIdx.x;
    float4 v = ((const float4*)x)[i];
    ((__nv_bfloat162*)g_xb)[2*i]   = __floats2bfloat162_rn(v.x, v.y);
    ((__nv_bfloat162*)g_xb)[2*i+1] = __floats2bfloat162_rn(v.z, v.w);
}
__global__ void kconv_w(const float* __restrict__ Wa, const float* __restrict__ Wb) {
    int i = blockIdx.x * blockDim.x + threadIdx.x;
    const float* src = (i < 16384) ? Wa : (i < 32768) ? Wb : (const float*)g_Wur;
    int j = i & 16383;
    float4 v = ((const float4*)src)[j];
    ((__nv_bfloat162*)g_Wbf)[2*i]   = __floats2bfloat162_rn(v.x, v.y);
    ((__nv_bfloat162*)g_Wbf)[2*i+1] = __floats2bfloat162_rn(v.z, v.w);
}

// ---------------- G1: projections. 128x128 CTA, 4 warps (2x2), 64x64 wtile --
__global__ __launch_bounds__(128) void g1_proj() {
    const int z = blockIdx.z;
    const __nv_bfloat16* __restrict__ W = g_Wbf + z*F*F;
    __nv_bfloat16* __restrict__ out = (z == 0) ? g_alpha : (z == 1) ? g_beta : g_up;

    const int row0 = blockIdx.x * 128;
    const int col0 = blockIdx.y * 128;
    __shared__ __nv_bfloat16 As[2][128][40];
    __shared__ __nv_bfloat16 Bs[2][128][40];

    const int tid = threadIdx.x, lane = tid & 31, wid = tid >> 5;
    const int wm = wid & 1, wn = wid >> 1;

    float acc[4][8][4];
    #pragma unroll
    for (int i = 0; i < 4; ++i)
        #pragma unroll
        for (int j = 0; j < 8; ++j)
            #pragma unroll
            for (int e = 0; e < 4; ++e) acc[i][j][e] = 0.f;

#define G1_LOAD(buf, kt) { \
    _Pragma("unroll") \
    for (int l = 0; l < 4; ++l) { \
        int id = tid + l*128; \
        int r = id >> 2, c8 = (id & 3)*8; \
        cp16(&As[buf][r][c8], &g_xb[(row0 + r)*F + (kt) + c8]); \
        cp16(&Bs[buf][r][c8], &W[(col0 + r)*F + (kt) + c8]); \
    } cp_commit(); }

    G1_LOAD(0, 0)
    const int NIT = F/32;
    for (int it = 0; it < NIT; ++it) {
        if (it + 1 < NIT) { G1_LOAD((it+1)&1, (it+1)*32) cp_wait1(); }
        else cp_wait0();
        __syncthreads();
        const int buf = it & 1;
        #pragma unroll
        for (int ks = 0; ks < 2; ++ks) {
            const int k0 = ks * 16;
            uint32_t a[4][4];
            #pragma unroll
            for (int mt = 0; mt < 4; ++mt)
                ldmx4(a[mt], cvta_s(&As[buf][wm*64 + mt*16 + (lane & 15)][k0 + (lane >> 4)*8]));
            uint32_t b[8][2];
            #pragma unroll
            for (int bt = 0; bt < 4; ++bt) {
                uint32_t t[4];
                int n  = wn*64 + bt*16 + (lane & 7) + ((lane >> 4) & 1)*8;
                int kk = k0 + ((lane >> 3) & 1)*8;
                ldmx4(t, cvta_s(&Bs[buf][n][kk]));
                b[bt*2][0] = t[0]; b[bt*2][1] = t[1];
                b[bt*2+1][0] = t[2]; b[bt*2+1][1] = t[3];
            }
            #pragma unroll
            for (int mt = 0; mt < 4; ++mt)
                #pragma unroll
                for (int nt = 0; nt < 8; ++nt)
                    mma_bf16(acc[mt][nt], a[mt], b[nt]);
        }
        __syncthreads();
    }
#undef G1_LOAD

    const int rc = lane >> 2, cc = (lane & 3)*2;
    #pragma unroll
    for (int mt = 0; mt < 4; ++mt) {
        int rb = row0 + wm*64 + mt*16 + rc;
        #pragma unroll
        for (int nt = 0; nt < 8; ++nt) {
            int col = col0 + wn*64 + nt*8 + cc;
            #pragma unroll
            for (int h = 0; h < 2; ++h) {
                int row = rb + h*8;
                float v0 = acc[mt][nt][2*h], v1 = acc[mt][nt][2*h+1];
                if (z == 2) { v0 += g_bp[col]; v1 += g_bp[col+1]; }
                *(__nv_bfloat162*)&out[row*F + col] = __floats2bfloat162_rn(v0, v1);
            }
        }
    }
}

// ---------------- kdiag ------------------------------------------------------
__global__ void kdiag() {
    int gw = (blockIdx.x * blockDim.x + threadIdx.x) >> 5;
    int lane = threadIdx.x & 31;
    const __nv_bfloat162* a = (const __nv_bfloat162*)(g_alpha + gw*F);
    const __nv_bfloat162* b = (const __nv_bfloat162*)(g_beta  + gw*F);
    float s = 0.f;
    #pragma unroll
    for (int t = lane; t < 128; t += 32) {
        float2 av = __bfloat1622float2(a[t]);
        float2 bv = __bfloat1622float2(b[t]);
        s = fmaf(av.x, bv.x, s);
        s = fmaf(av.y, bv.y, s);
    }
    #pragma unroll
    for (int o = 16; o > 0; o >>= 1) s += __shfl_xor_sync(0xffffffffu, s, o);
    if (lane == 0) g_d[gw] = s;
}

// ---------------- G2: M'[b] = beta^T @ up. 64x128 CTA, 4 warps, 32x64 wtile -
__global__ __launch_bounds__(128) void g2_mprime() {
    const int b  = blockIdx.z;
    const int m0 = blockIdx.x * 64;
    const int n0 = blockIdx.y * 128;
    const __nv_bfloat16* __restrict__ beta = g_beta + b*NTOK*F;
    const __nv_bfloat16* __restrict__ up   = g_up   + b*NTOK*F;

    __shared__ __nv_bfloat16 Bb[2][32][72];
    __shared__ __nv_bfloat16 Ub[2][32][136];

    const int tid = threadIdx.x, lane = tid & 31, wid = tid >> 5;
    const int wm = wid & 1, wn = wid >> 1;

    float acc[2][8][4];
    #pragma unroll
    for (int i = 0; i < 2; ++i)
        #pragma unroll
        for (int j = 0; j < 8; ++j)
            #pragma unroll
            for (int e = 0; e < 4; ++e) acc[i][j][e] = 0.f;

#define G2_LOAD(buf, rt) { \
    _Pragma("unroll") \
    for (int l = 0; l < 2; ++l) { \
        int id = tid + l*128; \
        int r = id >> 3, c8 = (id & 7)*8; \
        cp16(&Bb[buf][r][c8], &beta[((rt) + r)*F + m0 + c8]); \
    } \
    _Pragma("unroll") \
    for (int l = 0; l < 4; ++l) { \
        int id = tid + l*128; \
        int r = id >> 4, c8 = (id & 15)*8; \
        cp16(&Ub[buf][r][c8], &up[((rt) + r)*F + n0 + c8]); \
    } cp_commit(); }

    G2_LOAD(0, 0)
    const int NIT = NTOK/32;
    for (int it = 0; it < NIT; ++it) {
        if (it + 1 < NIT) { G2_LOAD((it+1)&1, (it+1)*32) cp_wait1(); }
        else cp_wait0();
        __syncthreads();
        const int buf = it & 1;
        #pragma unroll
        for (int ks = 0; ks < 2; ++ks) {
            const int r0 = ks * 16;
            uint32_t a[2][4];
            #pragma unroll
            for (int mt = 0; mt < 2; ++mt) {
                int rr = r0 + (lane & 7) + ((lane >> 4) & 1)*8;
                int cm = wm*32 + mt*16 + ((lane >> 3) & 1)*8;
                ldmx4t(a[mt], cvta_s(&Bb[buf][rr][cm]));
            }
            uint32_t bfr[8][2];
            #pragma unroll
            for (int bt = 0; bt < 4; ++bt) {
                uint32_t t[4];
                int rr = r0 + (lane & 7) + ((lane >> 3) & 1)*8;
                int cn = wn*64 + bt*16 + ((lane >> 4) & 1)*8;
                ldmx4t(t, cvta_s(&Ub[buf][rr][cn]));
                bfr[bt*2][0] = t[0]; bfr[bt*2][1] = t[1];
                bfr[bt*2+1][0] = t[2]; bfr[bt*2+1][1] = t[3];
            }
            #pragma unroll
            for (int mt = 0; mt < 2; ++mt)
                #pragma unroll
                for (int nt = 0; nt < 8; ++nt)
                    mma_bf16(acc[mt][nt], a[mt], bfr[nt]);
        }
        __syncthreads();
    }
#undef G2_LOAD

    const int rc = lane >> 2, cc = (lane & 3)*2;
    __nv_bfloat16* __restrict__ Mp = g_Mp + b*F*F;
    #pragma unroll
    for (int mt = 0; mt < 2; ++mt) {
        int rb = m0 + wm*32 + mt*16 + rc;
        #pragma unroll
        for (int nt = 0; nt < 8; ++nt) {
            int col = n0 + wn*64 + nt*8 + cc;
            #pragma unroll
            for (int h = 0; h < 2; ++h) {
                int row = rb + h*8;
                *(__nv_bfloat162*)&Mp[row*F + col] =
                    __floats2bfloat162_rn(acc[mt][nt][2*h], acc[mt][nt][2*h+1]);
            }
        }
    }
}

// ---------------- G3: out = (alpha @ M' - d*up)/N + x ------------------------
__global__ __launch_bounds__(128) void g3_out(const float* __restrict__ x,
                                              float* __restrict__ out) {
    const int row0 = blockIdx.x * 128;
    const int col0 = blockIdx.y * 128;
    const int b = row0 >> 10;
    const __nv_bfloat16* __restrict__ Mp = g_Mp + b*F*F;

    __shared__ __nv_bfloat16 As[2][128][40];
    __shared__ __nv_bfloat16 Ms[2][32][136];

    const int tid = threadIdx.x, lane = tid & 31, wid = tid >> 5;
    const int wm = wid & 1, wn = wid >> 1;

    float acc[4][8][4];
    #pragma unroll
    for (int i = 0; i < 4; ++i)
        #pragma unroll
        for (int j = 0; j < 8; ++j)
            #pragma unroll
            for (int e = 0; e < 4; ++e) acc[i][j][e] = 0.f;

#define G3_LOAD(buf, kt) { \
    _Pragma("unroll") \
    for (int l = 0; l < 4; ++l) { \
        int id = tid + l*128; \
        { int r = id >> 2, c8 = (id & 3)*8; \
          cp16(&As[buf][r][c8], &g_alpha[(row0 + r)*F + (kt) + c8]); } \
        { int r = id >> 4, c8 = (id & 15)*8; \
          cp16(&Ms[buf][r][c8], &Mp[((kt) + r)*F + col0 + c8]); } \
    } cp_commit(); }

    G3_LOAD(0, 0)
    const int NIT = F/32;
    for (int it = 0; it < NIT; ++it) {
        if (it + 1 < NIT) { G3_LOAD((it+1)&1, (it+1)*32) cp_wait1(); }
        else cp_wait0();
        __syncthreads();
        const int buf = it & 1;
        #pragma unroll
        for (int ks = 0; ks < 2; ++ks) {
            const int k0 = ks * 16;
            uint32_t a[4][4];
            #pragma unroll
            for (int mt = 0; mt < 4; ++mt)
                ldmx4(a[mt], cvta_s(&As[buf][wm*64 + mt*16 + (lane & 15)][k0 + (lane >> 4)*8]));
            uint32_t bfr[8][2];
            #pragma unroll
            for (int bt = 0; bt < 4; ++bt) {
                uint32_t t[4];
                int rr = k0 + (lane & 7) + ((lane >> 3) & 1)*8;
                int cn = wn*64 + bt*16 + ((lane >> 4) & 1)*8;
                ldmx4t(t, cvta_s(&Ms[buf][rr][cn]));
                bfr[bt*2][0] = t[0]; bfr[bt*2][1] = t[1];
                bfr[bt*2+1][0] = t[2]; bfr[bt*2+1][1] = t[3];
            }
            #pragma unroll
            for (int mt = 0; mt < 4; ++mt)
                #pragma unroll
                for (int nt = 0; nt < 8; ++nt)
                    mma_bf16(acc[mt][nt], a[mt], bfr[nt]);
        }
        __syncthreads();
    }
#undef G3_LOAD

    const float inv = 1.0f / (float)NTOK;
    const int rc = lane >> 2, cc = (lane & 3)*2;
    #pragma unroll
    for (int mt = 0; mt < 4; ++mt) {
        int rb = row0 + wm*64 + mt*16 + rc;
        #pragma unroll
        for (int h = 0; h < 2; ++h) {
            int row = rb + h*8;
            float di = g_d[row];
            #pragma unroll
            for (int nt = 0; nt < 8; ++nt) {
                int col = col0 + wn*64 + nt*8 + cc;
                float2 uv = __bfloat1622float2(*(const __nv_bfloat162*)&g_up[row*F + col]);
                float2 xv = *(const float2*)&x[row*F + col];
                float2 o;
                o.x = (acc[mt][nt][2*h]   - di*uv.x) * inv + xv.x;
                o.y = (acc[mt][nt][2*h+1] - di*uv.y) * inv + xv.y;
                *(float2*)&out[row*F + col] = o;
            }
        }
    }
}

// ---------------------------------------------------------------------------
extern "C" void kernel_launch(void* const* d_in, const int* in_sizes, int n_in,
                              void* d_out, int out_size) {
    const float* x  = (const float*)d_in[0];
    const float* Wa = (const float*)d_in[1];
    const float* Wb = (const float*)d_in[2];
    const float* Wu = (const float*)d_in[3];
    const float* bu = (const float*)d_in[4];
    const float* Wr = (const float*)d_in[5];
    float* out = (float*)d_out;

    k0_combine<<<F, F>>>(Wr, Wu, bu);
    kconv_x<<<ROWS*F/4/256, 256>>>(x);
    kconv_w<<<3*F*F/4/256, 256>>>(Wa, Wb);
    g1_proj<<<dim3(ROWS/128, F/128, 3), 128>>>();
    kdiag<<<ROWS*32/256, 256>>>();
    g2_mprime<<<dim3(F/64, F/128, NB), 128>>>();
    g3_out<<<dim3(ROWS/128, F/128), 128>>>(x, out);
}

// round 5
// speedup vs baseline: 4.4693x; 1.0442x over previous
#include <cuda_runtime.h>
#include <cuda_bf16.h>
#include <cstdint>

#define F 256
#define NTOK 1024
#define NB 16
#define ROWS (NB*NTOK)   // 16384

// ---------------- scratch (device globals; no allocation allowed) ----------
__device__ __nv_bfloat16 g_xb[ROWS*F];
__device__ __nv_bfloat16 g_alpha[ROWS*F];
__device__ __nv_bfloat16 g_beta[ROWS*F];
__device__ __nv_bfloat16 g_up[ROWS*F];
__device__ __nv_bfloat16 g_Mp[NB*F*F];       // M'_T[b][g][k]  (K-major)
__device__ __nv_bfloat16 g_Wbf[3*F*F];
__device__ float g_Wur[F*F];
__device__ float g_bp[F];
__device__ float g_d[ROWS];

// ---------------- helpers ----------------------------------------------------
__device__ __forceinline__ uint32_t cvta_s(const void* p) {
    return (uint32_t)__cvta_generic_to_shared(p);
}
__device__ __forceinline__ void cp16(void* s, const void* g) {
    asm volatile("cp.async.cg.shared.global [%0], [%1], 16;\n"
        :: "r"(cvta_s(s)), "l"(g));
}
__device__ __forceinline__ void cp_commit() { asm volatile("cp.async.commit_group;\n"); }
__device__ __forceinline__ void cp_wait1()  { asm volatile("cp.async.wait_group 1;\n"); }
__device__ __forceinline__ void cp_wait0()  { asm volatile("cp.async.wait_group 0;\n"); }

__device__ __forceinline__ void ldmx4(uint32_t r[4], uint32_t addr) {
    asm volatile("ldmatrix.sync.aligned.m8n8.x4.shared.b16 {%0,%1,%2,%3}, [%4];\n"
        : "=r"(r[0]), "=r"(r[1]), "=r"(r[2]), "=r"(r[3]) : "r"(addr));
}
__device__ __forceinline__ void ldmx4t(uint32_t r[4], uint32_t addr) {
    asm volatile("ldmatrix.sync.aligned.m8n8.x4.trans.shared.b16 {%0,%1,%2,%3}, [%4];\n"
        : "=r"(r[0]), "=r"(r[1]), "=r"(r[2]), "=r"(r[3]) : "r"(addr));
}
__device__ __forceinline__ void mma_bf16(float c[4], const uint32_t a[4], const uint32_t b[2]) {
    asm volatile(
        "mma.sync.aligned.m16n8k16.row.col.f32.bf16.bf16.f32 "
        "{%0,%1,%2,%3}, {%4,%5,%6,%7}, {%8,%9}, {%0,%1,%2,%3};\n"
        : "+f"(c[0]), "+f"(c[1]), "+f"(c[2]), "+f"(c[3])
        : "r"(a[0]), "r"(a[1]), "r"(a[2]), "r"(a[3]), "r"(b[0]), "r"(b[1]));
}

// ---------------- K0: combined weight ---------------------------------------
__global__ void k0_combine(const float* __restrict__ Wr,
                           const float* __restrict__ Wu,
                           const float* __restrict__ bu) {
    __shared__ float sWr[F];
    int g = blockIdx.x;
    int f = threadIdx.x;
    sWr[f] = Wr[g*F + f];
    __syncthreads();
    float acc = 0.f;
    #pragma unroll 8
    for (int h = 0; h < F; ++h) acc = fmaf(sWr[h], Wu[h*F + f], acc);
    g_Wur[g*F + f] = acc;
    if (f == 0) {
        float bb = 0.f;
        for (int h = 0; h < F; ++h) bb = fmaf(sWr[h], bu[h], bb);
        g_bp[g] = bb;
    }
}

// ---------------- conversions ------------------------------------------------
__global__ void kconv_x(const float* __restrict__ x) {
    int i = blockIdx.x * blockDim.x + threadIdx.x;
    float4 v = ((const float4*)x)[i];
    ((__nv_bfloat162*)g_xb)[2*i]   = __floats2bfloat162_rn(v.x, v.y);
    ((__nv_bfloat162*)g_xb)[2*i+1] = __floats2bfloat162_rn(v.z, v.w);
}
__global__ void kconv_w(const float* __restrict__ Wa, const float* __restrict__ Wb) {
    int i = blockIdx.x * blockDim.x + threadIdx.x;
    const float* src = (i < 16384) ? Wa : (i < 32768) ? Wb : (const float*)g_Wur;
    int j = i & 16383;
    float4 v = ((const float4*)src)[j];
    ((__nv_bfloat162*)g_Wbf)[2*i]   = __floats2bfloat162_rn(v.x, v.y);
    ((__nv_bfloat162*)g_Wbf)[2*i+1] = __floats2bfloat162_rn(v.z, v.w);
}

// ============================================================================
// Shared GEMM core: CTA 128(m) x 256(n), K-major operands, BK=32, 16 warps,
// warp tile 32x64. A rows from aG (row stride F), B rows from bG (row stride F).
// Dynamic smem: As[2][128][40] then Bs[2][256][40].
// Result left in acc[2][8][4]; caller does epilogue.
// ============================================================================
#define GEMM_CORE(aG, bG, NK) \
    __nv_bfloat16* As = (__nv_bfloat16*)smem_raw; \
    __nv_bfloat16* Bs = As + 2*128*40; \
    const int tid = threadIdx.x, lane = tid & 31, wid = tid >> 5; \
    const int wm = wid & 3, wn = wid >> 2; \
    float acc[2][8][4]; \
    _Pragma("unroll") \
    for (int i = 0; i < 2; ++i) \
        _Pragma("unroll") \
        for (int j = 0; j < 8; ++j) \
            _Pragma("unroll") \
            for (int e = 0; e < 4; ++e) acc[i][j][e] = 0.f; \
    { \
        int r = tid >> 2, c8 = (tid & 3)*8; \
        cp16(&As[(0*128 + r)*40 + c8], &(aG)[r*F + c8]); \
        int r2 = tid >> 1, c82 = (tid & 1)*16; \
        cp16(&Bs[(0*256 + r2)*40 + c82], &(bG)[r2*F + c82]); \
        cp16(&Bs[(0*256 + r2)*40 + c82 + 8], &(bG)[r2*F + c82 + 8]); \
        cp_commit(); \
    } \
    const int NIT = (NK)/32; \
    for (int it = 0; it < NIT; ++it) { \
        if (it + 1 < NIT) { \
            int kt = (it+1)*32, buf = (it+1)&1; \
            int r = tid >> 2, c8 = (tid & 3)*8; \
            cp16(&As[(buf*128 + r)*40 + c8], &(aG)[r*F + kt + c8]); \
            int r2 = tid >> 1, c82 = (tid & 1)*16; \
            cp16(&Bs[(buf*256 + r2)*40 + c82], &(bG)[r2*F + kt + c82]); \
            cp16(&Bs[(buf*256 + r2)*40 + c82 + 8], &(bG)[r2*F + kt + c82 + 8]); \
            cp_commit(); cp_wait1(); \
        } else cp_wait0(); \
        __syncthreads(); \
        const int buf = it & 1; \
        _Pragma("unroll") \
        for (int ks = 0; ks < 2; ++ks) { \
            const int k0 = ks * 16; \
            uint32_t afr[2][4]; \
            _Pragma("unroll") \
            for (int mt = 0; mt < 2; ++mt) \
                ldmx4(afr[mt], cvta_s(&As[(buf*128 + wm*32 + mt*16 + (lane & 15))*40 \
                                          + k0 + (lane >> 4)*8])); \
            uint32_t bfr[8][2]; \
            _Pragma("unroll") \
            for (int bt = 0; bt < 4; ++bt) { \
                uint32_t t[4]; \
                int n  = wn*64 + bt*16 + (lane & 7) + ((lane >> 4) & 1)*8; \
                int kk = k0 + ((lane >> 3) & 1)*8; \
                ldmx4(t, cvta_s(&Bs[(buf*256 + n)*40 + kk])); \
                bfr[bt*2][0] = t[0]; bfr[bt*2][1] = t[1]; \
                bfr[bt*2+1][0] = t[2]; bfr[bt*2+1][1] = t[3]; \
            } \
            _Pragma("unroll") \
            for (int mt = 0; mt < 2; ++mt) \
                _Pragma("unroll") \
                for (int nt = 0; nt < 8; ++nt) \
                    mma_bf16(acc[mt][nt], afr[mt], bfr[nt]); \
        } \
        __syncthreads(); \
    }

#define GEMM_SMEM (2*128*40*2 + 2*256*40*2)   // 61440 B

// ---------------- G1: projections. A = x-strip, B = W[z]. --------------------
__global__ __launch_bounds__(512, 1) void g1_proj() {
    extern __shared__ char smem_raw[];
    const int z = blockIdx.y;
    const int row0 = blockIdx.x * 128;
    const __nv_bfloat16* __restrict__ W = g_Wbf + z*F*F;
    __nv_bfloat16* __restrict__ out = (z == 0) ? g_alpha : (z == 1) ? g_beta : g_up;
    const __nv_bfloat16* aG = g_xb + row0*F;

    GEMM_CORE(aG, W, F)

    const int rc = lane >> 2, cc = (lane & 3)*2;
    #pragma unroll
    for (int mt = 0; mt < 2; ++mt) {
        int rb = row0 + wm*32 + mt*16 + rc;
        #pragma unroll
        for (int nt = 0; nt < 8; ++nt) {
            int col = wn*64 + nt*8 + cc;
            #pragma unroll
            for (int h = 0; h < 2; ++h) {
                int row = rb + h*8;
                float v0 = acc[mt][nt][2*h], v1 = acc[mt][nt][2*h+1];
                if (z == 2) { v0 += g_bp[col]; v1 += g_bp[col+1]; }
                *(__nv_bfloat162*)&out[row*F + col] = __floats2bfloat162_rn(v0, v1);
            }
        }
    }
}

// ---------------- kdiag ------------------------------------------------------
__global__ void kdiag() {
    int gw = (blockIdx.x * blockDim.x + threadIdx.x) >> 5;
    int lane = threadIdx.x & 31;
    const __nv_bfloat162* a = (const __nv_bfloat162*)(g_alpha + gw*F);
    const __nv_bfloat162* b = (const __nv_bfloat162*)(g_beta  + gw*F);
    float s = 0.f;
    #pragma unroll
    for (int t = lane; t < 128; t += 32) {
        float2 av = __bfloat1622float2(a[t]);
        float2 bv = __bfloat1622float2(b[t]);
        s = fmaf(av.x, bv.x, s);
        s = fmaf(av.y, bv.y, s);
    }
    #pragma unroll
    for (int o = 16; o > 0; o >>= 1) s += __shfl_xor_sync(0xffffffffu, s, o);
    if (lane == 0) g_d[gw] = s;
}

// ---------------- G2 (roles swapped): M'_T[g][k] = sum_n up[n,g]*beta[n,k] ---
__global__ __launch_bounds__(128) void g2_mprime() {
    const int b  = blockIdx.z;
    const int m0 = blockIdx.x * 64;        // g
    const int n0 = blockIdx.y * 128;       // k
    const __nv_bfloat16* __restrict__ Aop = g_up   + b*NTOK*F;
    const __nv_bfloat16* __restrict__ Bop = g_beta + b*NTOK*F;

    __shared__ __nv_bfloat16 Bb[2][32][72];
    __shared__ __nv_bfloat16 Ub[2][32][136];

    const int tid = threadIdx.x, lane = tid & 31, wid = tid >> 5;
    const int wm = wid & 1, wn = wid >> 1;

    float acc[2][8][4];
    #pragma unroll
    for (int i = 0; i < 2; ++i)
        #pragma unroll
        for (int j = 0; j < 8; ++j)
            #pragma unroll
            for (int e = 0; e < 4; ++e) acc[i][j][e] = 0.f;

#define G2_LOAD(buf, rt) { \
    _Pragma("unroll") \
    for (int l = 0; l < 2; ++l) { \
        int id = tid + l*128; \
        int r = id >> 3, c8 = (id & 7)*8; \
        cp16(&Bb[buf][r][c8], &Aop[((rt) + r)*F + m0 + c8]); \
    } \
    _Pragma("unroll") \
    for (int l = 0; l < 4; ++l) { \
        int id = tid + l*128; \
        int r = id >> 4, c8 = (id & 15)*8; \
        cp16(&Ub[buf][r][c8], &Bop[((rt) + r)*F + n0 + c8]); \
    } cp_commit(); }

    G2_LOAD(0, 0)
    const int NIT = NTOK/32;
    for (int it = 0; it < NIT; ++it) {
        if (it + 1 < NIT) { G2_LOAD((it+1)&1, (it+1)*32) cp_wait1(); }
        else cp_wait0();
        __syncthreads();
        const int buf = it & 1;
        #pragma unroll
        for (int ks = 0; ks < 2; ++ks) {
            const int r0 = ks * 16;
            uint32_t a[2][4];
            #pragma unroll
            for (int mt = 0; mt < 2; ++mt) {
                int rr = r0 + (lane & 7) + ((lane >> 4) & 1)*8;
                int cm = wm*32 + mt*16 + ((lane >> 3) & 1)*8;
                ldmx4t(a[mt], cvta_s(&Bb[buf][rr][cm]));
            }
            uint32_t bfr[8][2];
            #pragma unroll
            for (int bt = 0; bt < 4; ++bt) {
                uint32_t t[4];
                int rr = r0 + (lane & 7) + ((lane >> 3) & 1)*8;
                int cn = wn*64 + bt*16 + ((lane >> 4) & 1)*8;
                ldmx4t(t, cvta_s(&Ub[buf][rr][cn]));
                bfr[bt*2][0] = t[0]; bfr[bt*2][1] = t[1];
                bfr[bt*2+1][0] = t[2]; bfr[bt*2+1][1] = t[3];
            }
            #pragma unroll
            for (int mt = 0; mt < 2; ++mt)
                #pragma unroll
                for (int nt = 0; nt < 8; ++nt)
                    mma_bf16(acc[mt][nt], a[mt], bfr[nt]);
        }
        __syncthreads();
    }
#undef G2_LOAD

    const int rc = lane >> 2, cc = (lane & 3)*2;
    __nv_bfloat16* __restrict__ Mp = g_Mp + b*F*F;
    #pragma unroll
    for (int mt = 0; mt < 2; ++mt) {
        int rb = m0 + wm*32 + mt*16 + rc;
        #pragma unroll
        for (int nt = 0; nt < 8; ++nt) {
            int col = n0 + wn*64 + nt*8 + cc;
            #pragma unroll
            for (int h = 0; h < 2; ++h) {
                int row = rb + h*8;
                *(__nv_bfloat162*)&Mp[row*F + col] =
                    __floats2bfloat162_rn(acc[mt][nt][2*h], acc[mt][nt][2*h+1]);
            }
        }
    }
}

// ---------------- G3: out = (alpha @ M'_T^T - d*up)/N + x --------------------
__global__ __launch_bounds__(512, 1) void g3_out(const float* __restrict__ x,
                                                 float* __restrict__ out) {
    extern __shared__ char smem_raw[];
    const int row0 = blockIdx.x * 128;
    const int b = row0 >> 10;
    const __nv_bfloat16* __restrict__ Mp = g_Mp + b*F*F;   // [g][k] K-major
    const __nv_bfloat16* aG = g_alpha + row0*F;

    GEMM_CORE(aG, Mp, F)

    const float inv = 1.0f / (float)NTOK;
    const int rc = lane >> 2, cc = (lane & 3)*2;
    #pragma unroll
    for (int mt = 0; mt < 2; ++mt) {
        int rb = row0 + wm*32 + mt*16 + rc;
        #pragma unroll
        for (int h = 0; h < 2; ++h) {
            int row = rb + h*8;
            float di = g_d[row];
            #pragma unroll
            for (int nt = 0; nt < 8; ++nt) {
                int col = wn*64 + nt*8 + cc;
                float2 uv = __bfloat1622float2(*(const __nv_bfloat162*)&g_up[row*F + col]);
                float2 xv = *(const float2*)&x[row*F + col];
                float2 o;
                o.x = (acc[mt][nt][2*h]   - di*uv.x) * inv + xv.x;
                o.y = (acc[mt][nt][2*h+1] - di*uv.y) * inv + xv.y;
                *(float2*)&out[row*F + col] = o;
            }
        }
    }
}

// ---------------------------------------------------------------------------
extern "C" void kernel_launch(void* const* d_in, const int* in_sizes, int n_in,
                              void* d_out, int out_size) {
    const float* x  = (const float*)d_in[0];
    const float* Wa = (const float*)d_in[1];
    const float* Wb = (const float*)d_in[2];
    const float* Wu = (const float*)d_in[3];
    const float* bu = (const float*)d_in[4];
    const float* Wr = (const float*)d_in[5];
    float* out = (float*)d_out;

    static int smem_set = 0;
    if (!smem_set) {
        cudaFuncSetAttribute(g1_proj, cudaFuncAttributeMaxDynamicSharedMemorySize, GEMM_SMEM);
        cudaFuncSetAttribute(g3_out, cudaFuncAttributeMaxDynamicSharedMemorySize, GEMM_SMEM);
        smem_set = 1;
    }

    k0_combine<<<F, F>>>(Wr, Wu, bu);
    kconv_x<<<ROWS*F/4/256, 256>>>(x);
    kconv_w<<<3*F*F/4/256, 256>>>(Wa, Wb);
    g1_proj<<<dim3(ROWS/128, 3), 512, GEMM_SMEM>>>();
    kdiag<<<ROWS*32/256, 256>>>();
    g2_mprime<<<dim3(F/64, F/128, NB), 128>>>();
    g3_out<<<ROWS/128, 512, GEMM_SMEM>>>(x, out);
}

// round 6
// speedup vs baseline: 4.5574x; 1.0197x over previous
#include <cuda_runtime.h>
#include <cuda_bf16.h>
#include <cstdint>

#define F 256
#define NTOK 1024
#define NB 16
#define ROWS (NB*NTOK)   // 16384

// ---------------- scratch ----------------------------------------------------
__device__ __nv_bfloat16 g_xb[ROWS*F];
__device__ __nv_bfloat16 g_alpha[ROWS*F];
__device__ __nv_bfloat16 g_beta[ROWS*F];
__device__ __nv_bfloat16 g_up[ROWS*F];
__device__ __nv_bfloat16 g_Mp[NB*F*F];       // M'_T[b][g][k]  (K-major)
__device__ __nv_bfloat16 g_Wbf[3*F*F];
__device__ float g_Wur[F*F];
__device__ float g_bp[F];
__device__ float g_d[ROWS];

// ---------------- helpers ----------------------------------------------------
__device__ __forceinline__ uint32_t cvta_s(const void* p) {
    return (uint32_t)__cvta_generic_to_shared(p);
}
__device__ __forceinline__ void cp16(void* s, const void* g) {
    asm volatile("cp.async.cg.shared.global [%0], [%1], 16;\n"
        :: "r"(cvta_s(s)), "l"(g));
}
__device__ __forceinline__ void cp_commit() { asm volatile("cp.async.commit_group;\n"); }
__device__ __forceinline__ void cp_wait1()  { asm volatile("cp.async.wait_group 1;\n"); }
__device__ __forceinline__ void cp_wait0()  { asm volatile("cp.async.wait_group 0;\n"); }

__device__ __forceinline__ void ldmx4(uint32_t r[4], uint32_t addr) {
    asm volatile("ldmatrix.sync.aligned.m8n8.x4.shared.b16 {%0,%1,%2,%3}, [%4];\n"
        : "=r"(r[0]), "=r"(r[1]), "=r"(r[2]), "=r"(r[3]) : "r"(addr));
}
__device__ __forceinline__ void ldmx4t(uint32_t r[4], uint32_t addr) {
    asm volatile("ldmatrix.sync.aligned.m8n8.x4.trans.shared.b16 {%0,%1,%2,%3}, [%4];\n"
        : "=r"(r[0]), "=r"(r[1]), "=r"(r[2]), "=r"(r[3]) : "r"(addr));
}
__device__ __forceinline__ void mma_bf16(float c[4], const uint32_t a[4], const uint32_t b[2]) {
    asm volatile(
        "mma.sync.aligned.m16n8k16.row.col.f32.bf16.bf16.f32 "
        "{%0,%1,%2,%3}, {%4,%5,%6,%7}, {%8,%9}, {%0,%1,%2,%3};\n"
        : "+f"(c[0]), "+f"(c[1]), "+f"(c[2]), "+f"(c[3])
        : "r"(a[0]), "r"(a[1]), "r"(a[2]), "r"(a[3]), "r"(b[0]), "r"(b[1]));
}

// ---------------- K0: combined weight ---------------------------------------
__global__ void k0_combine(const float* __restrict__ Wr,
                           const float* __restrict__ Wu,
                           const float* __restrict__ bu) {
    __shared__ float sWr[F];
    int g = blockIdx.x;
    int f = threadIdx.x;
    sWr[f] = Wr[g*F + f];
    __syncthreads();
    float acc = 0.f;
    #pragma unroll 8
    for (int h = 0; h < F; ++h) acc = fmaf(sWr[h], Wu[h*F + f], acc);
    g_Wur[g*F + f] = acc;
    if (f == 0) {
        float bb = 0.f;
        for (int h = 0; h < F; ++h) bb = fmaf(sWr[h], bu[h], bb);
        g_bp[g] = bb;
    }
}

// ---------------- conversions ------------------------------------------------
__global__ void kconv_x(const float* __restrict__ x) {
    int i = blockIdx.x * blockDim.x + threadIdx.x;
    float4 v = ((const float4*)x)[i];
    ((__nv_bfloat162*)g_xb)[2*i]   = __floats2bfloat162_rn(v.x, v.y);
    ((__nv_bfloat162*)g_xb)[2*i+1] = __floats2bfloat162_rn(v.z, v.w);
}
__global__ void kconv_w(const float* __restrict__ Wa, const float* __restrict__ Wb) {
    int i = blockIdx.x * blockDim.x + threadIdx.x;
    const float* src = (i < 16384) ? Wa : (i < 32768) ? Wb : (const float*)g_Wur;
    int j = i & 16383;
    float4 v = ((const float4*)src)[j];
    ((__nv_bfloat162*)g_Wbf)[2*i]   = __floats2bfloat162_rn(v.x, v.y);
    ((__nv_bfloat162*)g_Wbf)[2*i+1] = __floats2bfloat162_rn(v.z, v.w);
}

// ============================================================================
// GEMM core: CTA 128(m) x 128(n), BK=64, 8 warps (4m x 2n), warp tile 32x64.
// K-major operands. Smem double-buffered (72 KB), register frags
// double-buffered across the 4 k-steps of each chunk.
// Leaves result in acc[2][8][4].
// ============================================================================
#define LDSTRIDE 72

#define LOAD_FRAGS(dst_a, dst_b, buf, k0) { \
    _Pragma("unroll") \
    for (int mt = 0; mt < 2; ++mt) \
        ldmx4(dst_a[mt], cvta_s(&As[((buf)*128 + wm*32 + mt*16 + (lane & 15))*LDSTRIDE \
                                    + (k0) + (lane >> 4)*8])); \
    _Pragma("unroll") \
    for (int bt = 0; bt < 4; ++bt) { \
        uint32_t t[4]; \
        int n  = wn*64 + bt*16 + (lane & 7) + ((lane >> 4) & 1)*8; \
        int kk = (k0) + ((lane >> 3) & 1)*8; \
        ldmx4(t, cvta_s(&Bs[((buf)*128 + n)*LDSTRIDE + kk])); \
        dst_b[bt*2][0] = t[0]; dst_b[bt*2][1] = t[1]; \
        dst_b[bt*2+1][0] = t[2]; dst_b[bt*2+1][1] = t[3]; \
    } }

#define GEMM_CORE(aG, bG, NK) \
    __nv_bfloat16* As = (__nv_bfloat16*)smem_raw; \
    __nv_bfloat16* Bs = As + 2*128*LDSTRIDE; \
    const int tid = threadIdx.x, lane = tid & 31, wid = tid >> 5; \
    const int wm = wid & 3, wn = wid >> 2; \
    float acc[2][8][4]; \
    _Pragma("unroll") \
    for (int i = 0; i < 2; ++i) \
        _Pragma("unroll") \
        for (int j = 0; j < 8; ++j) \
            _Pragma("unroll") \
            for (int e = 0; e < 4; ++e) acc[i][j][e] = 0.f; \
    { \
        int r = tid >> 3, c8 = (tid & 7)*8; \
        _Pragma("unroll") \
        for (int l = 0; l < 4; ++l) { \
            cp16(&As[(0*128 + r + l*32)*LDSTRIDE + c8], &(aG)[(r + l*32)*F + c8]); \
            cp16(&Bs[(0*128 + r + l*32)*LDSTRIDE + c8], &(bG)[(r + l*32)*F + c8]); \
        } \
        cp_commit(); \
    } \
    const int NIT = (NK)/64; \
    for (int it = 0; it < NIT; ++it) { \
        if (it + 1 < NIT) { \
            int kt = (it+1)*64, buf = (it+1)&1; \
            int r = tid >> 3, c8 = (tid & 7)*8; \
            _Pragma("unroll") \
            for (int l = 0; l < 4; ++l) { \
                cp16(&As[(buf*128 + r + l*32)*LDSTRIDE + c8], &(aG)[(r + l*32)*F + kt + c8]); \
                cp16(&Bs[(buf*128 + r + l*32)*LDSTRIDE + c8], &(bG)[(r + l*32)*F + kt + c8]); \
            } \
            cp_commit(); cp_wait1(); \
        } else cp_wait0(); \
        __syncthreads(); \
        const int buf = it & 1; \
        uint32_t afr[2][2][4]; \
        uint32_t bfr[2][8][2]; \
        LOAD_FRAGS(afr[0], bfr[0], buf, 0) \
        _Pragma("unroll") \
        for (int ks = 0; ks < 4; ++ks) { \
            const int cur = ks & 1, nxt = cur ^ 1; \
            if (ks < 3) LOAD_FRAGS(afr[nxt], bfr[nxt], buf, (ks+1)*16) \
            _Pragma("unroll") \
            for (int mt = 0; mt < 2; ++mt) \
                _Pragma("unroll") \
                for (int nt = 0; nt < 8; ++nt) \
                    mma_bf16(acc[mt][nt], afr[cur][mt], bfr[cur][nt]); \
        } \
        __syncthreads(); \
    }

#define GEMM_SMEM (2*128*LDSTRIDE*2*2)   // 73728 B

// ---------------- G1: projections --------------------------------------------
__global__ __launch_bounds__(256, 2) void g1_proj() {
    extern __shared__ char smem_raw[];
    const int z = blockIdx.z;
    const int row0 = blockIdx.x * 128;
    const int col0 = blockIdx.y * 128;
    const __nv_bfloat16* __restrict__ W = g_Wbf + z*F*F;
    __nv_bfloat16* __restrict__ out = (z == 0) ? g_alpha : (z == 1) ? g_beta : g_up;
    const __nv_bfloat16* aG = g_xb + row0*F;
    const __nv_bfloat16* bG = W + col0*F;

    GEMM_CORE(aG, bG, F)

    const int rc = lane >> 2, cc = (lane & 3)*2;
    #pragma unroll
    for (int mt = 0; mt < 2; ++mt) {
        int rb = row0 + wm*32 + mt*16 + rc;
        #pragma unroll
        for (int nt = 0; nt < 8; ++nt) {
            int col = col0 + wn*64 + nt*8 + cc;
            #pragma unroll
            for (int h = 0; h < 2; ++h) {
                int row = rb + h*8;
                float v0 = acc[mt][nt][2*h], v1 = acc[mt][nt][2*h+1];
                if (z == 2) { v0 += g_bp[col]; v1 += g_bp[col+1]; }
                *(__nv_bfloat162*)&out[row*F + col] = __floats2bfloat162_rn(v0, v1);
            }
        }
    }
}

// ---------------- kdiag ------------------------------------------------------
__global__ void kdiag() {
    int gw = (blockIdx.x * blockDim.x + threadIdx.x) >> 5;
    int lane = threadIdx.x & 31;
    const __nv_bfloat162* a = (const __nv_bfloat162*)(g_alpha + gw*F);
    const __nv_bfloat162* b = (const __nv_bfloat162*)(g_beta  + gw*F);
    float s = 0.f;
    #pragma unroll
    for (int t = lane; t < 128; t += 32) {
        float2 av = __bfloat1622float2(a[t]);
        float2 bv = __bfloat1622float2(b[t]);
        s = fmaf(av.x, bv.x, s);
        s = fmaf(av.y, bv.y, s);
    }
    #pragma unroll
    for (int o = 16; o > 0; o >>= 1) s += __shfl_xor_sync(0xffffffffu, s, o);
    if (lane == 0) g_d[gw] = s;
}

// ---------------- G2 (roles swapped): M'_T[g][k] = sum_n up[n,g]*beta[n,k] ---
__global__ __launch_bounds__(128) void g2_mprime() {
    const int b  = blockIdx.z;
    const int m0 = blockIdx.x * 64;        // g
    const int n0 = blockIdx.y * 128;       // k
    const __nv_bfloat16* __restrict__ Aop = g_up   + b*NTOK*F;
    const __nv_bfloat16* __restrict__ Bop = g_beta + b*NTOK*F;

    __shared__ __nv_bfloat16 Bb[2][32][72];
    __shared__ __nv_bfloat16 Ub[2][32][136];

    const int tid = threadIdx.x, lane = tid & 31, wid = tid >> 5;
    const int wm = wid & 1, wn = wid >> 1;

    float acc[2][8][4];
    #pragma unroll
    for (int i = 0; i < 2; ++i)
        #pragma unroll
        for (int j = 0; j < 8; ++j)
            #pragma unroll
            for (int e = 0; e < 4; ++e) acc[i][j][e] = 0.f;

#define G2_LOAD(buf, rt) { \
    _Pragma("unroll") \
    for (int l = 0; l < 2; ++l) { \
        int id = tid + l*128; \
        int r = id >> 3, c8 = (id & 7)*8; \
        cp16(&Bb[buf][r][c8], &Aop[((rt) + r)*F + m0 + c8]); \
    } \
    _Pragma("unroll") \
    for (int l = 0; l < 4; ++l) { \
        int id = tid + l*128; \
        int r = id >> 4, c8 = (id & 15)*8; \
        cp16(&Ub[buf][r][c8], &Bop[((rt) + r)*F + n0 + c8]); \
    } cp_commit(); }

    G2_LOAD(0, 0)
    const int NIT = NTOK/32;
    for (int it = 0; it < NIT; ++it) {
        if (it + 1 < NIT) { G2_LOAD((it+1)&1, (it+1)*32) cp_wait1(); }
        else cp_wait0();
        __syncthreads();
        const int buf = it & 1;
        #pragma unroll
        for (int ks = 0; ks < 2; ++ks) {
            const int r0 = ks * 16;
            uint32_t a[2][4];
            #pragma unroll
            for (int mt = 0; mt < 2; ++mt) {
                int rr = r0 + (lane & 7) + ((lane >> 4) & 1)*8;
                int cm = wm*32 + mt*16 + ((lane >> 3) & 1)*8;
                ldmx4t(a[mt], cvta_s(&Bb[buf][rr][cm]));
            }
            uint32_t bfr[8][2];
            #pragma unroll
            for (int bt = 0; bt < 4; ++bt) {
                uint32_t t[4];
                int rr = r0 + (lane & 7) + ((lane >> 3) & 1)*8;
                int cn = wn*64 + bt*16 + ((lane >> 4) & 1)*8;
                ldmx4t(t, cvta_s(&Ub[buf][rr][cn]));
                bfr[bt*2][0] = t[0]; bfr[bt*2][1] = t[1];
                bfr[bt*2+1][0] = t[2]; bfr[bt*2+1][1] = t[3];
            }
            #pragma unroll
            for (int mt = 0; mt < 2; ++mt)
                #pragma unroll
                for (int nt = 0; nt < 8; ++nt)
                    mma_bf16(acc[mt][nt], a[mt], bfr[nt]);
        }
        __syncthreads();
    }
#undef G2_LOAD

    const int rc = lane >> 2, cc = (lane & 3)*2;
    __nv_bfloat16* __restrict__ Mp = g_Mp + b*F*F;
    #pragma unroll
    for (int mt = 0; mt < 2; ++mt) {
        int rb = m0 + wm*32 + mt*16 + rc;
        #pragma unroll
        for (int nt = 0; nt < 8; ++nt) {
            int col = n0 + wn*64 + nt*8 + cc;
            #pragma unroll
            for (int h = 0; h < 2; ++h) {
                int row = rb + h*8;
                *(__nv_bfloat162*)&Mp[row*F + col] =
                    __floats2bfloat162_rn(acc[mt][nt][2*h], acc[mt][nt][2*h+1]);
            }
        }
    }
}

// ---------------- G3: out = (alpha @ M'_T^T - d*up)/N + x --------------------
__global__ __launch_bounds__(256, 2) void g3_out(const float* __restrict__ x,
                                                 float* __restrict__ out) {
    extern __shared__ char smem_raw[];
    const int row0 = blockIdx.x * 128;
    const int col0 = blockIdx.y * 128;
    const int b = row0 >> 10;
    const __nv_bfloat16* __restrict__ Mp = g_Mp + b*F*F;   // [g][k] K-major
    const __nv_bfloat16* aG = g_alpha + row0*F;
    const __nv_bfloat16* bG = Mp + col0*F;

    GEMM_CORE(aG, bG, F)

    const float inv = 1.0f / (float)NTOK;
    const int rc = lane >> 2, cc = (lane & 3)*2;
    #pragma unroll
    for (int mt = 0; mt < 2; ++mt) {
        int rb = row0 + wm*32 + mt*16 + rc;
        #pragma unroll
        for (int h = 0; h < 2; ++h) {
            int row = rb + h*8;
            float di = g_d[row];
            #pragma unroll
            for (int nt = 0; nt < 8; ++nt) {
                int col = col0 + wn*64 + nt*8 + cc;
                float2 uv = __bfloat1622float2(*(const __nv_bfloat162*)&g_up[row*F + col]);
                float2 xv = *(const float2*)&x[row*F + col];
                float2 o;
                o.x = (acc[mt][nt][2*h]   - di*uv.x) * inv + xv.x;
                o.y = (acc[mt][nt][2*h+1] - di*uv.y) * inv + xv.y;
                *(float2*)&out[row*F + col] = o;
            }
        }
    }
}

// ---------------------------------------------------------------------------
extern "C" void kernel_launch(void* const* d_in, const int* in_sizes, int n_in,
                              void* d_out, int out_size) {
    const float* x  = (const float*)d_in[0];
    const float* Wa = (const float*)d_in[1];
    const float* Wb = (const float*)d_in[2];
    const float* Wu = (const float*)d_in[3];
    const float* bu = (const float*)d_in[4];
    const float* Wr = (const float*)d_in[5];
    float* out = (float*)d_out;

    static int smem_set = 0;
    if (!smem_set) {
        cudaFuncSetAttribute(g1_proj, cudaFuncAttributeMaxDynamicSharedMemorySize, GEMM_SMEM);
        cudaFuncSetAttribute(g3_out, cudaFuncAttributeMaxDynamicSharedMemorySize, GEMM_SMEM);
        smem_set = 1;
    }

    k0_combine<<<F, F>>>(Wr, Wu, bu);
    kconv_x<<<ROWS*F/4/256, 256>>>(x);
    kconv_w<<<3*F*F/4/256, 256>>>(Wa, Wb);
    g1_proj<<<dim3(ROWS/128, F/128, 3), 256, GEMM_SMEM>>>();
    kdiag<<<ROWS*32/256, 256>>>();
    g2_mprime<<<dim3(F/64, F/128, NB), 128>>>();
    g3_out<<<dim3(ROWS/128, F/128), 256, GEMM_SMEM>>>(x, out);
}

// round 8
// speedup vs baseline: 4.8897x; 1.0729x over previous
#include <cuda_runtime.h>
#include <cuda_bf16.h>
#include <cstdint>

#define F 256
#define NTOK 1024
#define NB 16
#define ROWS (NB*NTOK)   // 16384

// ---------------- scratch ----------------------------------------------------
__device__ __nv_bfloat16 g_xb[ROWS*F];
__device__ __nv_bfloat16 g_alpha[ROWS*F];
__device__ __nv_bfloat16 g_beta[ROWS*F];
__device__ __nv_bfloat16 g_up[ROWS*F];
__device__ __nv_bfloat16 g_Mp[NB*F*F];       // M'_T[b][g][k]  (K-major)
__device__ __nv_bfloat16 g_Wbf[3*F*F];
__device__ float g_Wur[F*F];
__device__ float g_bp[F];
__device__ float g_d[ROWS];

// ---------------- helpers ----------------------------------------------------
__device__ __forceinline__ uint32_t cvta_s(const void* p) {
    return (uint32_t)__cvta_generic_to_shared(p);
}
__device__ __forceinline__ void cp16(void* s, const void* g) {
    asm volatile("cp.async.cg.shared.global [%0], [%1], 16;\n"
        :: "r"(cvta_s(s)), "l"(g));
}
__device__ __forceinline__ void cp_commit() { asm volatile("cp.async.commit_group;\n"); }
__device__ __forceinline__ void cp_wait1()  { asm volatile("cp.async.wait_group 1;\n"); }
__device__ __forceinline__ void cp_wait0()  { asm volatile("cp.async.wait_group 0;\n"); }

__device__ __forceinline__ void ldmx4(uint32_t r[4], uint32_t addr) {
    asm volatile("ldmatrix.sync.aligned.m8n8.x4.shared.b16 {%0,%1,%2,%3}, [%4];\n"
        : "=r"(r[0]), "=r"(r[1]), "=r"(r[2]), "=r"(r[3]) : "r"(addr));
}
__device__ __forceinline__ void ldmx4t(uint32_t r[4], uint32_t addr) {
    asm volatile("ldmatrix.sync.aligned.m8n8.x4.trans.shared.b16 {%0,%1,%2,%3}, [%4];\n"
        : "=r"(r[0]), "=r"(r[1]), "=r"(r[2]), "=r"(r[3]) : "r"(addr));
}
__device__ __forceinline__ void mma_bf16(float c[4], const uint32_t a[4], const uint32_t b[2]) {
    asm volatile(
        "mma.sync.aligned.m16n8k16.row.col.f32.bf16.bf16.f32 "
        "{%0,%1,%2,%3}, {%4,%5,%6,%7}, {%8,%9}, {%0,%1,%2,%3};\n"
        : "+f"(c[0]), "+f"(c[1]), "+f"(c[2]), "+f"(c[3])
        : "r"(a[0]), "r"(a[1]), "r"(a[2]), "r"(a[3]), "r"(b[0]), "r"(b[1]));
}

// ---------------- K0: combined weight ---------------------------------------
__global__ void k0_combine(const float* __restrict__ Wr,
                           const float* __restrict__ Wu,
                           const float* __restrict__ bu) {
    __shared__ float sWr[F];
    int g = blockIdx.x;
    int f = threadIdx.x;
    sWr[f] = Wr[g*F + f];
    __syncthreads();
    float acc = 0.f;
    #pragma unroll 8
    for (int h = 0; h < F; ++h) acc = fmaf(sWr[h], Wu[h*F + f], acc);
    g_Wur[g*F + f] = acc;
    if (f == 0) {
        float bb = 0.f;
        for (int h = 0; h < F; ++h) bb = fmaf(sWr[h], bu[h], bb);
        g_bp[g] = bb;
    }
}

// ---------------- conversions ------------------------------------------------
__global__ void kconv_x(const float* __restrict__ x) {
    int i = blockIdx.x * blockDim.x + threadIdx.x;
    float4 v = ((const float4*)x)[i];
    ((__nv_bfloat162*)g_xb)[2*i]   = __floats2bfloat162_rn(v.x, v.y);
    ((__nv_bfloat162*)g_xb)[2*i+1] = __floats2bfloat162_rn(v.z, v.w);
}
__global__ void kconv_w(const float* __restrict__ Wa, const float* __restrict__ Wb) {
    int i = blockIdx.x * blockDim.x + threadIdx.x;
    const float* src = (i < 16384) ? Wa : (i < 32768) ? Wb : (const float*)g_Wur;
    int j = i & 16383;
    float4 v = ((const float4*)src)[j];
    ((__nv_bfloat162*)g_Wbf)[2*i]   = __floats2bfloat162_rn(v.x, v.y);
    ((__nv_bfloat162*)g_Wbf)[2*i+1] = __floats2bfloat162_rn(v.z, v.w);
}

// ============================================================================
// GEMM core (R6-proven ordering): CTA 128x128, BK=64, 8 warps (4m x 2n),
// warp tile 32x64. Smem + register-fragment double buffering.
// ============================================================================
#define LDSTRIDE 72

#define LOAD_FRAGS(dst_a, dst_b, buf, k0) { \
    _Pragma("unroll") \
    for (int mt = 0; mt < 2; ++mt) \
        ldmx4(dst_a[mt], cvta_s(&As[((buf)*128 + wm*32 + mt*16 + (lane & 15))*LDSTRIDE \
                                    + (k0) + (lane >> 4)*8])); \
    _Pragma("unroll") \
    for (int bt = 0; bt < 4; ++bt) { \
        uint32_t t[4]; \
        int n  = wn*64 + bt*16 + (lane & 7) + ((lane >> 4) & 1)*8; \
        int kk = (k0) + ((lane >> 3) & 1)*8; \
        ldmx4(t, cvta_s(&Bs[((buf)*128 + n)*LDSTRIDE + kk])); \
        dst_b[bt*2][0] = t[0]; dst_b[bt*2][1] = t[1]; \
        dst_b[bt*2+1][0] = t[2]; dst_b[bt*2+1][1] = t[3]; \
    } }

#define GEMM_CORE(aG, bG, NK) \
    __nv_bfloat16* As = (__nv_bfloat16*)smem_raw; \
    __nv_bfloat16* Bs = As + 2*128*LDSTRIDE; \
    const int tid = threadIdx.x, lane = tid & 31, wid = tid >> 5; \
    const int wm = wid & 3, wn = wid >> 2; \
    float acc[2][8][4]; \
    _Pragma("unroll") \
    for (int i = 0; i < 2; ++i) \
        _Pragma("unroll") \
        for (int j = 0; j < 8; ++j) \
            _Pragma("unroll") \
            for (int e = 0; e < 4; ++e) acc[i][j][e] = 0.f; \
    { \
        int r = tid >> 3, c8 = (tid & 7)*8; \
        _Pragma("unroll") \
        for (int l = 0; l < 4; ++l) { \
            cp16(&As[(0*128 + r + l*32)*LDSTRIDE + c8], &(aG)[(r + l*32)*F + c8]); \
            cp16(&Bs[(0*128 + r + l*32)*LDSTRIDE + c8], &(bG)[(r + l*32)*F + c8]); \
        } \
        cp_commit(); \
    } \
    const int NIT = (NK)/64; \
    for (int it = 0; it < NIT; ++it) { \
        if (it + 1 < NIT) { \
            int kt = (it+1)*64, buf = (it+1)&1; \
            int r = tid >> 3, c8 = (tid & 7)*8; \
            _Pragma("unroll") \
            for (int l = 0; l < 4; ++l) { \
                cp16(&As[(buf*128 + r + l*32)*LDSTRIDE + c8], &(aG)[(r + l*32)*F + kt + c8]); \
                cp16(&Bs[(buf*128 + r + l*32)*LDSTRIDE + c8], &(bG)[(r + l*32)*F + kt + c8]); \
            } \
            cp_commit(); cp_wait1(); \
        } else cp_wait0(); \
        __syncthreads(); \
        const int buf = it & 1; \
        uint32_t afr[2][2][4]; \
        uint32_t bfr[2][8][2]; \
        LOAD_FRAGS(afr[0], bfr[0], buf, 0) \
        _Pragma("unroll") \
        for (int ks = 0; ks < 4; ++ks) { \
            const int cur = ks & 1, nxt = cur ^ 1; \
            if (ks < 3) LOAD_FRAGS(afr[nxt], bfr[nxt], buf, (ks+1)*16) \
            _Pragma("unroll") \
            for (int mt = 0; mt < 2; ++mt) \
                _Pragma("unroll") \
                for (int nt = 0; nt < 8; ++nt) \
                    mma_bf16(acc[mt][nt], afr[cur][mt], bfr[cur][nt]); \
        } \
        __syncthreads(); \
    }

#define GEMM_SMEM (2*128*LDSTRIDE*2*2)   // 73728 B

// ---------------- G1: projections --------------------------------------------
__global__ __launch_bounds__(256, 2) void g1_proj() {
    extern __shared__ char smem_raw[];
    const int z = blockIdx.z;
    const int row0 = blockIdx.x * 128;
    const int col0 = blockIdx.y * 128;
    const __nv_bfloat16* __restrict__ W = g_Wbf + z*F*F;
    __nv_bfloat16* __restrict__ out = (z == 0) ? g_alpha : (z == 1) ? g_beta : g_up;
    const __nv_bfloat16* aG = g_xb + row0*F;
    const __nv_bfloat16* bG = W + col0*F;

    GEMM_CORE(aG, bG, F)

    const int rc = lane >> 2, cc = (lane & 3)*2;
    #pragma unroll
    for (int mt = 0; mt < 2; ++mt) {
        int rb = row0 + wm*32 + mt*16 + rc;
        #pragma unroll
        for (int nt = 0; nt < 8; ++nt) {
            int col = col0 + wn*64 + nt*8 + cc;
            #pragma unroll
            for (int h = 0; h < 2; ++h) {
                int row = rb + h*8;
                float v0 = acc[mt][nt][2*h], v1 = acc[mt][nt][2*h+1];
                if (z == 2) { v0 += g_bp[col]; v1 += g_bp[col+1]; }
                *(__nv_bfloat162*)&out[row*F + col] = __floats2bfloat162_rn(v0, v1);
            }
        }
    }
}

// ---------------- kdiag ------------------------------------------------------
__global__ void kdiag() {
    int gw = (blockIdx.x * blockDim.x + threadIdx.x) >> 5;
    int lane = threadIdx.x & 31;
    const __nv_bfloat162* a = (const __nv_bfloat162*)(g_alpha + gw*F);
    const __nv_bfloat162* b = (const __nv_bfloat162*)(g_beta  + gw*F);
    float s = 0.f;
    #pragma unroll
    for (int t = lane; t < 128; t += 32) {
        float2 av = __bfloat1622float2(a[t]);
        float2 bv = __bfloat1622float2(b[t]);
        s = fmaf(av.x, bv.x, s);
        s = fmaf(av.y, bv.y, s);
    }
    #pragma unroll
    for (int o = 16; o > 0; o >>= 1) s += __shfl_xor_sync(0xffffffffu, s, o);
    if (lane == 0) g_d[gw] = s;
}

// ---------------- G2: M'_T[g][k] = sum_n up[n,g]*beta[n,k] -------------------
// 64x64 tiles, grid (4,4,16) = 256 CTAs, 128 threads, warp tile 32x32, BK=32.
__global__ __launch_bounds__(128) void g2_mprime() {
    const int b  = blockIdx.z;
    const int m0 = blockIdx.x * 64;        // g
    const int n0 = blockIdx.y * 64;        // k
    const __nv_bfloat16* __restrict__ Aop = g_up   + b*NTOK*F;
    const __nv_bfloat16* __restrict__ Bop = g_beta + b*NTOK*F;

    __shared__ __nv_bfloat16 Ut[2][32][72];
    __shared__ __nv_bfloat16 Bt[2][32][72];

    const int tid = threadIdx.x, lane = tid & 31, wid = tid >> 5;
    const int wm = wid & 1, wn = wid >> 1;

    float acc[2][4][4];
    #pragma unroll
    for (int i = 0; i < 2; ++i)
        #pragma unroll
        for (int j = 0; j < 4; ++j)
            #pragma unroll
            for (int e = 0; e < 4; ++e) acc[i][j][e] = 0.f;

#define G2_LOAD(buf, rt) { \
    _Pragma("unroll") \
    for (int l = 0; l < 2; ++l) { \
        int id = tid + l*128; \
        int r = id >> 3, c8 = (id & 7)*8; \
        cp16(&Ut[buf][r][c8], &Aop[((rt) + r)*F + m0 + c8]); \
        cp16(&Bt[buf][r][c8], &Bop[((rt) + r)*F + n0 + c8]); \
    } cp_commit(); }

    G2_LOAD(0, 0)
    const int NIT = NTOK/32;
    for (int it = 0; it < NIT; ++it) {
        if (it + 1 < NIT) { G2_LOAD((it+1)&1, (it+1)*32) cp_wait1(); }
        else cp_wait0();
        __syncthreads();
        const int buf = it & 1;
        #pragma unroll
        for (int ks = 0; ks < 2; ++ks) {
            const int r0 = ks * 16;
            uint32_t a[2][4];
            #pragma unroll
            for (int mt = 0; mt < 2; ++mt) {
                int rr = r0 + (lane & 7) + ((lane >> 4) & 1)*8;
                int cm = wm*32 + mt*16 + ((lane >> 3) & 1)*8;
                ldmx4t(a[mt], cvta_s(&Ut[buf][rr][cm]));
            }
            uint32_t bfr[4][2];
            {
                uint32_t t[4];
                int rr = r0 + (lane & 7) + ((lane >> 3) & 1)*8;
                #pragma unroll
                for (int bt = 0; bt < 2; ++bt) {
                    int cn = wn*32 + bt*16 + ((lane >> 4) & 1)*8;
                    ldmx4t(t, cvta_s(&Bt[buf][rr][cn]));
                    bfr[bt*2][0] = t[0]; bfr[bt*2][1] = t[1];
                    bfr[bt*2+1][0] = t[2]; bfr[bt*2+1][1] = t[3];
                }
            }
            #pragma unroll
            for (int mt = 0; mt < 2; ++mt)
                #pragma unroll
                for (int nt = 0; nt < 4; ++nt)
                    mma_bf16(acc[mt][nt], a[mt], bfr[nt]);
        }
        __syncthreads();
    }
#undef G2_LOAD

    const int rc = lane >> 2, cc = (lane & 3)*2;
    __nv_bfloat16* __restrict__ Mp = g_Mp + b*F*F;
    #pragma unroll
    for (int mt = 0; mt < 2; ++mt) {
        int rb = m0 + wm*32 + mt*16 + rc;
        #pragma unroll
        for (int nt = 0; nt < 4; ++nt) {
            int col = n0 + wn*32 + nt*8 + cc;
            #pragma unroll
            for (int h = 0; h < 2; ++h) {
                int row = rb + h*8;
                *(__nv_bfloat162*)&Mp[row*F + col] =
                    __floats2bfloat162_rn(acc[mt][nt][2*h], acc[mt][nt][2*h+1]);
            }
        }
    }
}

// ---------------- G3: out = (alpha @ M'_T^T - d*up)/N + x --------------------
__global__ __launch_bounds__(256, 2) void g3_out(const float* __restrict__ x,
                                                 float* __restrict__ out) {
    extern __shared__ char smem_raw[];
    const int row0 = blockIdx.x * 128;
    const int col0 = blockIdx.y * 128;
    const int b = row0 >> 10;
    const __nv_bfloat16* __restrict__ Mp = g_Mp + b*F*F;   // [g][k] K-major
    const __nv_bfloat16* aG = g_alpha + row0*F;
    const __nv_bfloat16* bG = Mp + col0*F;

    GEMM_CORE(aG, bG, F)

    const float inv = 1.0f / (float)NTOK;
    const int rc = lane >> 2, cc = (lane & 3)*2;
    #pragma unroll
    for (int mt = 0; mt < 2; ++mt) {
        int rb = row0 + wm*32 + mt*16 + rc;
        #pragma unroll
        for (int h = 0; h < 2; ++h) {
            int row = rb + h*8;
            float di = g_d[row];
            #pragma unroll
            for (int nt = 0; nt < 8; ++nt) {
                int col = col0 + wn*64 + nt*8 + cc;
                float2 uv = __bfloat1622float2(*(const __nv_bfloat162*)&g_up[row*F + col]);
                float2 xv = *(const float2*)&x[row*F + col];
                float2 o;
                o.x = (acc[mt][nt][2*h]   - di*uv.x) * inv + xv.x;
                o.y = (acc[mt][nt][2*h+1] - di*uv.y) * inv + xv.y;
                *(float2*)&out[row*F + col] = o;
            }
        }
    }
}

// ---------------------------------------------------------------------------
extern "C" void kernel_launch(void* const* d_in, const int* in_sizes, int n_in,
                              void* d_out, int out_size) {
    const float* x  = (const float*)d_in[0];
    const float* Wa = (const float*)d_in[1];
    const float* Wb = (const float*)d_in[2];
    const float* Wu = (const float*)d_in[3];
    const float* bu = (const float*)d_in[4];
    const float* Wr = (const float*)d_in[5];
    float* out = (float*)d_out;

    static int smem_set = 0;
    if (!smem_set) {
        cudaFuncSetAttribute(g1_proj, cudaFuncAttributeMaxDynamicSharedMemorySize, GEMM_SMEM);
        cudaFuncSetAttribute(g3_out, cudaFuncAttributeMaxDynamicSharedMemorySize, GEMM_SMEM);
        smem_set = 1;
    }

    k0_combine<<<F, F>>>(Wr, Wu, bu);
    kconv_x<<<ROWS*F/4/256, 256>>>(x);
    kconv_w<<<3*F*F/4/256, 256>>>(Wa, Wb);
    g1_proj<<<dim3(ROWS/128, F/128, 3), 256, GEMM_SMEM>>>();
    kdiag<<<ROWS*32/256, 256>>>();
    g2_mprime<<<dim3(F/64, F/64, NB), 128>>>();
    g3_out<<<dim3(ROWS/128, F/128), 256, GEMM_SMEM>>>(x, out);
}

// round 9
// speedup vs baseline: 5.1566x; 1.0546x over previous
#include <cuda_runtime.h>
#include <cuda_bf16.h>
#include <cstdint>

#define F 256
#define NTOK 1024
#define NB 16
#define ROWS (NB*NTOK)   // 16384

// ---------------- scratch ----------------------------------------------------
__device__ __nv_bfloat16 g_xb[ROWS*F];
__device__ __nv_bfloat16 g_alpha[ROWS*F];
__device__ __nv_bfloat16 g_beta[ROWS*F];
__device__ __nv_bfloat16 g_up[ROWS*F];
__device__ __nv_bfloat16 g_Mp[NB*F*F];       // M'_T[b][g][k]  (K-major)
__device__ __nv_bfloat16 g_Wbf[3*F*F];
__device__ float g_Wur[F*F];
__device__ float g_bp[F];
__device__ float g_d[ROWS];

// ---------------- helpers ----------------------------------------------------
__device__ __forceinline__ uint32_t cvta_s(const void* p) {
    return (uint32_t)__cvta_generic_to_shared(p);
}
__device__ __forceinline__ void cp16(void* s, const void* g) {
    asm volatile("cp.async.cg.shared.global [%0], [%1], 16;\n"
        :: "r"(cvta_s(s)), "l"(g));
}
__device__ __forceinline__ void cp_commit() { asm volatile("cp.async.commit_group;\n"); }
__device__ __forceinline__ void cp_wait1()  { asm volatile("cp.async.wait_group 1;\n"); }
__device__ __forceinline__ void cp_wait0()  { asm volatile("cp.async.wait_group 0;\n"); }

__device__ __forceinline__ void ldmx4(uint32_t r[4], uint32_t addr) {
    asm volatile("ldmatrix.sync.aligned.m8n8.x4.shared.b16 {%0,%1,%2,%3}, [%4];\n"
        : "=r"(r[0]), "=r"(r[1]), "=r"(r[2]), "=r"(r[3]) : "r"(addr));
}
__device__ __forceinline__ void ldmx4t(uint32_t r[4], uint32_t addr) {
    asm volatile("ldmatrix.sync.aligned.m8n8.x4.trans.shared.b16 {%0,%1,%2,%3}, [%4];\n"
        : "=r"(r[0]), "=r"(r[1]), "=r"(r[2]), "=r"(r[3]) : "r"(addr));
}
__device__ __forceinline__ void mma_bf16(float c[4], const uint32_t a[4], const uint32_t b[2]) {
    asm volatile(
        "mma.sync.aligned.m16n8k16.row.col.f32.bf16.bf16.f32 "
        "{%0,%1,%2,%3}, {%4,%5,%6,%7}, {%8,%9}, {%0,%1,%2,%3};\n"
        : "+f"(c[0]), "+f"(c[1]), "+f"(c[2]), "+f"(c[3])
        : "r"(a[0]), "r"(a[1]), "r"(a[2]), "r"(a[3]), "r"(b[0]), "r"(b[1]));
}

// ---------------- K0: combined weight ---------------------------------------
__global__ void k0_combine(const float* __restrict__ Wr,
                           const float* __restrict__ Wu,
                           const float* __restrict__ bu) {
    __shared__ float sWr[F];
    int g = blockIdx.x;
    int f = threadIdx.x;
    sWr[f] = Wr[g*F + f];
    __syncthreads();
    float acc = 0.f;
    #pragma unroll 8
    for (int h = 0; h < F; ++h) acc = fmaf(sWr[h], Wu[h*F + f], acc);
    g_Wur[g*F + f] = acc;
    if (f == 0) {
        float bb = 0.f;
        for (int h = 0; h < F; ++h) bb = fmaf(sWr[h], bu[h], bb);
        g_bp[g] = bb;
    }
}

// ---------------- conversions ------------------------------------------------
__global__ void kconv_x(const float* __restrict__ x) {
    int i = blockIdx.x * blockDim.x + threadIdx.x;
    float4 v = ((const float4*)x)[i];
    ((__nv_bfloat162*)g_xb)[2*i]   = __floats2bfloat162_rn(v.x, v.y);
    ((__nv_bfloat162*)g_xb)[2*i+1] = __floats2bfloat162_rn(v.z, v.w);
}
__global__ void kconv_w(const float* __restrict__ Wa, const float* __restrict__ Wb) {
    int i = blockIdx.x * blockDim.x + threadIdx.x;
    const float* src = (i < 16384) ? Wa : (i < 32768) ? Wb : (const float*)g_Wur;
    int j = i & 16383;
    float4 v = ((const float4*)src)[j];
    ((__nv_bfloat162*)g_Wbf)[2*i]   = __floats2bfloat162_rn(v.x, v.y);
    ((__nv_bfloat162*)g_Wbf)[2*i+1] = __floats2bfloat162_rn(v.z, v.w);
}

// ============================================================================
// GEMM core (R6-proven ordering): CTA 128x128, BK=64, 8 warps (4m x 2n),
// warp tile 32x64. Smem + register-fragment double buffering.
// ============================================================================
#define LDSTRIDE 72

#define LOAD_FRAGS(dst_a, dst_b, buf, k0) { \
    _Pragma("unroll") \
    for (int mt = 0; mt < 2; ++mt) \
        ldmx4(dst_a[mt], cvta_s(&As[((buf)*128 + wm*32 + mt*16 + (lane & 15))*LDSTRIDE \
                                    + (k0) + (lane >> 4)*8])); \
    _Pragma("unroll") \
    for (int bt = 0; bt < 4; ++bt) { \
        uint32_t t[4]; \
        int n  = wn*64 + bt*16 + (lane & 7) + ((lane >> 4) & 1)*8; \
        int kk = (k0) + ((lane >> 3) & 1)*8; \
        ldmx4(t, cvta_s(&Bs[((buf)*128 + n)*LDSTRIDE + kk])); \
        dst_b[bt*2][0] = t[0]; dst_b[bt*2][1] = t[1]; \
        dst_b[bt*2+1][0] = t[2]; dst_b[bt*2+1][1] = t[3]; \
    } }

#define GEMM_CORE(aG, bG, NK) \
    __nv_bfloat16* As = (__nv_bfloat16*)smem_raw; \
    __nv_bfloat16* Bs = As + 2*128*LDSTRIDE; \
    const int tid = threadIdx.x, lane = tid & 31, wid = tid >> 5; \
    const int wm = wid & 3, wn = wid >> 2; \
    float acc[2][8][4]; \
    _Pragma("unroll") \
    for (int i = 0; i < 2; ++i) \
        _Pragma("unroll") \
        for (int j = 0; j < 8; ++j) \
            _Pragma("unroll") \
            for (int e = 0; e < 4; ++e) acc[i][j][e] = 0.f; \
    { \
        int r = tid >> 3, c8 = (tid & 7)*8; \
        _Pragma("unroll") \
        for (int l = 0; l < 4; ++l) { \
            cp16(&As[(0*128 + r + l*32)*LDSTRIDE + c8], &(aG)[(r + l*32)*F + c8]); \
            cp16(&Bs[(0*128 + r + l*32)*LDSTRIDE + c8], &(bG)[(r + l*32)*F + c8]); \
        } \
        cp_commit(); \
    } \
    const int NIT = (NK)/64; \
    for (int it = 0; it < NIT; ++it) { \
        if (it + 1 < NIT) { \
            int kt = (it+1)*64, buf = (it+1)&1; \
            int r = tid >> 3, c8 = (tid & 7)*8; \
            _Pragma("unroll") \
            for (int l = 0; l < 4; ++l) { \
                cp16(&As[(buf*128 + r + l*32)*LDSTRIDE + c8], &(aG)[(r + l*32)*F + kt + c8]); \
                cp16(&Bs[(buf*128 + r + l*32)*LDSTRIDE + c8], &(bG)[(r + l*32)*F + kt + c8]); \
            } \
            cp_commit(); cp_wait1(); \
        } else cp_wait0(); \
        __syncthreads(); \
        const int buf = it & 1; \
        uint32_t afr[2][2][4]; \
        uint32_t bfr[2][8][2]; \
        LOAD_FRAGS(afr[0], bfr[0], buf, 0) \
        _Pragma("unroll") \
        for (int ks = 0; ks < 4; ++ks) { \
            const int cur = ks & 1, nxt = cur ^ 1; \
            if (ks < 3) LOAD_FRAGS(afr[nxt], bfr[nxt], buf, (ks+1)*16) \
            _Pragma("unroll") \
            for (int mt = 0; mt < 2; ++mt) \
                _Pragma("unroll") \
                for (int nt = 0; nt < 8; ++nt) \
                    mma_bf16(acc[mt][nt], afr[cur][mt], bfr[cur][nt]); \
        } \
        __syncthreads(); \
    }

#define GEMM_SMEM (2*128*LDSTRIDE*2*2)   // 73728 B

// ---------------- G1: projections --------------------------------------------
__global__ __launch_bounds__(256, 2) void g1_proj() {
    extern __shared__ char smem_raw[];
    const int z = blockIdx.z;
    const int row0 = blockIdx.x * 128;
    const int col0 = blockIdx.y * 128;
    const __nv_bfloat16* __restrict__ W = g_Wbf + z*F*F;
    __nv_bfloat16* __restrict__ out = (z == 0) ? g_alpha : (z == 1) ? g_beta : g_up;
    const __nv_bfloat16* aG = g_xb + row0*F;
    const __nv_bfloat16* bG = W + col0*F;

    GEMM_CORE(aG, bG, F)

    const int rc = lane >> 2, cc = (lane & 3)*2;
    #pragma unroll
    for (int mt = 0; mt < 2; ++mt) {
        int rb = row0 + wm*32 + mt*16 + rc;
        #pragma unroll
        for (int nt = 0; nt < 8; ++nt) {
            int col = col0 + wn*64 + nt*8 + cc;
            #pragma unroll
            for (int h = 0; h < 2; ++h) {
                int row = rb + h*8;
                float v0 = acc[mt][nt][2*h], v1 = acc[mt][nt][2*h+1];
                if (z == 2) { v0 += g_bp[col]; v1 += g_bp[col+1]; }
                *(__nv_bfloat162*)&out[row*F + col] = __floats2bfloat162_rn(v0, v1);
            }
        }
    }
}

// ---------------- kdiag ------------------------------------------------------
__global__ void kdiag() {
    int gw = (blockIdx.x * blockDim.x + threadIdx.x) >> 5;
    int lane = threadIdx.x & 31;
    const __nv_bfloat162* a = (const __nv_bfloat162*)(g_alpha + gw*F);
    const __nv_bfloat162* b = (const __nv_bfloat162*)(g_beta  + gw*F);
    float s = 0.f;
    #pragma unroll
    for (int t = lane; t < 128; t += 32) {
        float2 av = __bfloat1622float2(a[t]);
        float2 bv = __bfloat1622float2(b[t]);
        s = fmaf(av.x, bv.x, s);
        s = fmaf(av.y, bv.y, s);
    }
    #pragma unroll
    for (int o = 16; o > 0; o >>= 1) s += __shfl_xor_sync(0xffffffffu, s, o);
    if (lane == 0) g_d[gw] = s;
}

// ---------------- G2: M'_T[g][k] = sum_n up[n,g]*beta[n,k] -------------------
// 64x64 tiles, grid (4,4,16) = 256 CTAs, 128 threads, warp tile 32x32, BK=32.
__global__ __launch_bounds__(128) void g2_mprime() {
    const int b  = blockIdx.z;
    const int m0 = blockIdx.x * 64;        // g
    const int n0 = blockIdx.y * 64;        // k
    const __nv_bfloat16* __restrict__ Aop = g_up   + b*NTOK*F;
    const __nv_bfloat16* __restrict__ Bop = g_beta + b*NTOK*F;

    __shared__ __nv_bfloat16 Ut[2][32][72];
    __shared__ __nv_bfloat16 Bt[2][32][72];

    const int tid = threadIdx.x, lane = tid & 31, wid = tid >> 5;
    const int wm = wid & 1, wn = wid >> 1;

    float acc[2][4][4];
    #pragma unroll
    for (int i = 0; i < 2; ++i)
        #pragma unroll
        for (int j = 0; j < 4; ++j)
            #pragma unroll
            for (int e = 0; e < 4; ++e) acc[i][j][e] = 0.f;

#define G2_LOAD(buf, rt) { \
    _Pragma("unroll") \
    for (int l = 0; l < 2; ++l) { \
        int id = tid + l*128; \
        int r = id >> 3, c8 = (id & 7)*8; \
        cp16(&Ut[buf][r][c8], &Aop[((rt) + r)*F + m0 + c8]); \
        cp16(&Bt[buf][r][c8], &Bop[((rt) + r)*F + n0 + c8]); \
    } cp_commit(); }

    G2_LOAD(0, 0)
    const int NIT = NTOK/32;
    for (int it = 0; it < NIT; ++it) {
        if (it + 1 < NIT) { G2_LOAD((it+1)&1, (it+1)*32) cp_wait1(); }
        else cp_wait0();
        __syncthreads();
        const int buf = it & 1;
        #pragma unroll
        for (int ks = 0; ks < 2; ++ks) {
            const int r0 = ks * 16;
            uint32_t a[2][4];
            #pragma unroll
            for (int mt = 0; mt < 2; ++mt) {
                int rr = r0 + (lane & 7) + ((lane >> 4) & 1)*8;
                int cm = wm*32 + mt*16 + ((lane >> 3) & 1)*8;
                ldmx4t(a[mt], cvta_s(&Ut[buf][rr][cm]));
            }
            uint32_t bfr[4][2];
            {
                uint32_t t[4];
                int rr = r0 + (lane & 7) + ((lane >> 3) & 1)*8;
                #pragma unroll
                for (int bt = 0; bt < 2; ++bt) {
                    int cn = wn*32 + bt*16 + ((lane >> 4) & 1)*8;
                    ldmx4t(t, cvta_s(&Bt[buf][rr][cn]));
                    bfr[bt*2][0] = t[0]; bfr[bt*2][1] = t[1];
                    bfr[bt*2+1][0] = t[2]; bfr[bt*2+1][1] = t[3];
                }
            }
            #pragma unroll
            for (int mt = 0; mt < 2; ++mt)
                #pragma unroll
                for (int nt = 0; nt < 4; ++nt)
                    mma_bf16(acc[mt][nt], a[mt], bfr[nt]);
        }
        __syncthreads();
    }
#undef G2_LOAD

    const int rc = lane >> 2, cc = (lane & 3)*2;
    __nv_bfloat16* __restrict__ Mp = g_Mp + b*F*F;
    #pragma unroll
    for (int mt = 0; mt < 2; ++mt) {
        int rb = m0 + wm*32 + mt*16 + rc;
        #pragma unroll
        for (int nt = 0; nt < 4; ++nt) {
            int col = n0 + wn*32 + nt*8 + cc;
            #pragma unroll
            for (int h = 0; h < 2; ++h) {
                int row = rb + h*8;
                *(__nv_bfloat162*)&Mp[row*F + col] =
                    __floats2bfloat162_rn(acc[mt][nt][2*h], acc[mt][nt][2*h+1]);
            }
        }
    }
}

// ---------------- G3: out = (alpha @ M'_T^T - d*up)/N + x --------------------
__global__ __launch_bounds__(256, 2) void g3_out(const float* __restrict__ x,
                                                 float* __restrict__ out) {
    extern __shared__ char smem_raw[];
    const int row0 = blockIdx.x * 128;
    const int col0 = blockIdx.y * 128;
    const int b = row0 >> 10;
    const __nv_bfloat16* __restrict__ Mp = g_Mp + b*F*F;   // [g][k] K-major
    const __nv_bfloat16* aG = g_alpha + row0*F;
    const __nv_bfloat16* bG = Mp + col0*F;

    GEMM_CORE(aG, bG, F)

    const float inv = 1.0f / (float)NTOK;
    const int rc = lane >> 2, cc = (lane & 3)*2;
    #pragma unroll
    for (int mt = 0; mt < 2; ++mt) {
        int rb = row0 + wm*32 + mt*16 + rc;
        #pragma unroll
        for (int h = 0; h < 2; ++h) {
            int row = rb + h*8;
            float di = g_d[row];
            #pragma unroll
            for (int nt = 0; nt < 8; ++nt) {
                int col = col0 + wn*64 + nt*8 + cc;
                float2 uv = __bfloat1622float2(*(const __nv_bfloat162*)&g_up[row*F + col]);
                float2 xv = *(const float2*)&x[row*F + col];
                float2 o;
                o.x = (acc[mt][nt][2*h]   - di*uv.x) * inv + xv.x;
                o.y = (acc[mt][nt][2*h+1] - di*uv.y) * inv + xv.y;
                *(float2*)&out[row*F + col] = o;
            }
        }
    }
}

// ---------------------------------------------------------------------------
extern "C" void kernel_launch(void* const* d_in, const int* in_sizes, int n_in,
                              void* d_out, int out_size) {
    const float* x  = (const float*)d_in[0];
    const float* Wa = (const float*)d_in[1];
    const float* Wb = (const float*)d_in[2];
    const float* Wu = (const float*)d_in[3];
    const float* bu = (const float*)d_in[4];
    const float* Wr = (const float*)d_in[5];
    float* out = (float*)d_out;

    static int inited = 0;
    static cudaStream_t s2;
    static cudaEvent_t eA, eB, eC, eD;
    if (!inited) {
        cudaFuncSetAttribute(g1_proj, cudaFuncAttributeMaxDynamicSharedMemorySize, GEMM_SMEM);
        cudaFuncSetAttribute(g3_out, cudaFuncAttributeMaxDynamicSharedMemorySize, GEMM_SMEM);
        cudaStreamCreateWithFlags(&s2, cudaStreamNonBlocking);
        cudaEventCreateWithFlags(&eA, cudaEventDisableTiming);
        cudaEventCreateWithFlags(&eB, cudaEventDisableTiming);
        cudaEventCreateWithFlags(&eC, cudaEventDisableTiming);
        cudaEventCreateWithFlags(&eD, cudaEventDisableTiming);
        inited = 1;
    }

    // fork: kconv_x on s2 || (k0 -> kconv_w) on main
    cudaEventRecord(eA, 0);
    cudaStreamWaitEvent(s2, eA, 0);
    kconv_x<<<ROWS*F/4/256, 256, 0, s2>>>(x);
    k0_combine<<<F, F>>>(Wr, Wu, bu);
    kconv_w<<<3*F*F/4/256, 256>>>(Wa, Wb);
    cudaEventRecord(eB, s2);
    cudaStreamWaitEvent(0, eB, 0);

    g1_proj<<<dim3(ROWS/128, F/128, 3), 256, GEMM_SMEM>>>();

    // fork: kdiag on s2 || g2 on main
    cudaEventRecord(eC, 0);
    cudaStreamWaitEvent(s2, eC, 0);
    kdiag<<<ROWS*32/256, 256, 0, s2>>>();
    g2_mprime<<<dim3(F/64, F/64, NB), 128>>>();
    cudaEventRecord(eD, s2);
    cudaStreamWaitEvent(0, eD, 0);

    g3_out<<<dim3(ROWS/128, F/128), 256, GEMM_SMEM>>>(x, out);
}